// round 1
// baseline (speedup 1.0000x reference)
#include <cuda_runtime.h>

#define B_  4
#define T_  2048
#define C_  768
#define H_  12
#define HS_ 64
#define BH_ (B_*H_)

// Scratch (no allocations allowed): Q,K,V,O in [B,H,T,HS] layout
__device__ float g_q[BH_*T_*HS_];
__device__ float g_k[BH_*T_*HS_];
__device__ float g_v[BH_*T_*HS_];
__device__ float g_o[BH_*T_*HS_];

// ---------------------------------------------------------------------------
// QKV GEMM: X[8192,768] @ W_attn[768,2304] + b_attn, scattered into g_q/g_k/g_v
// 128x128x16 tile, 256 threads, 8x8 register micro-tile.
// ---------------------------------------------------------------------------
__global__ __launch_bounds__(256) void qkv_gemm(const float* __restrict__ X,
                                                const float* __restrict__ W,
                                                const float* __restrict__ bias)
{
    const int N = 3 * C_;   // 2304
    const int K = C_;       // 768
    __shared__ float As[128][17];   // [m][k], pad to kill read conflicts
    __shared__ float Bs[16][128];   // [k][n]

    const int tid = threadIdx.x;
    const int tx = tid & 15, ty = tid >> 4;
    const int M0 = blockIdx.y * 128;
    const int N0 = blockIdx.x * 128;

    float acc[8][8];
#pragma unroll
    for (int i = 0; i < 8; i++)
#pragma unroll
        for (int j = 0; j < 8; j++) acc[i][j] = 0.f;

    const int am = tid >> 2;          // 0..63
    const int ak = (tid & 3) * 4;     // 0,4,8,12
    const int bk = tid >> 5;          // 0..7
    const int bn = (tid & 31) * 4;    // 0..124

    for (int k0 = 0; k0 < K; k0 += 16) {
#pragma unroll
        for (int r = 0; r < 2; r++) {
            int m = am + r * 64;
            float4 v = *reinterpret_cast<const float4*>(X + (size_t)(M0 + m) * K + k0 + ak);
            As[m][ak + 0] = v.x; As[m][ak + 1] = v.y;
            As[m][ak + 2] = v.z; As[m][ak + 3] = v.w;
        }
#pragma unroll
        for (int r = 0; r < 2; r++) {
            int kk = bk + r * 8;
            *reinterpret_cast<float4*>(&Bs[kk][bn]) =
                *reinterpret_cast<const float4*>(W + (size_t)(k0 + kk) * N + N0 + bn);
        }
        __syncthreads();
#pragma unroll
        for (int kk = 0; kk < 16; kk++) {
            float a[8], b[8];
#pragma unroll
            for (int i = 0; i < 8; i++) a[i] = As[ty + 16 * i][kk];
#pragma unroll
            for (int j = 0; j < 8; j++) b[j] = Bs[kk][tx + 16 * j];
#pragma unroll
            for (int i = 0; i < 8; i++)
#pragma unroll
                for (int j = 0; j < 8; j++) acc[i][j] = fmaf(a[i], b[j], acc[i][j]);
        }
        __syncthreads();
    }

    // Epilogue: + bias, scatter into per-head layout [B,H,T,HS]
#pragma unroll
    for (int i = 0; i < 8; i++) {
        int mg = M0 + ty + 16 * i;
        int bi = mg >> 11;            // /2048
        int t  = mg & (T_ - 1);
#pragma unroll
        for (int j = 0; j < 8; j++) {
            int ng = N0 + tx + 16 * j;
            float val = acc[i][j] + bias[ng];
            int which = ng / C_;       // 0=q,1=k,2=v
            int c = ng - which * C_;
            int h = c >> 6, hs = c & 63;
            float* dst = (which == 0) ? g_q : (which == 1 ? g_k : g_v);
            dst[((size_t)(bi * H_ + h) * T_ + t) * HS_ + hs] = val;
        }
    }
}

// ---------------------------------------------------------------------------
// Flash attention (fp32): one block per (b*h, 64-row q tile).
// smem: Q[64][65] (pre-scaled), Kt[64][65] (reused for P), V[64][65].
// Online softmax; row reductions via 16-lane shfl butterflies.
// ---------------------------------------------------------------------------
#define ATT_SMEM (3 * 64 * 65 * 4)

__global__ __launch_bounds__(256) void attn_kernel()
{
    extern __shared__ float sm[];
    float* sQ  = sm;                 // [64][65], Q * scale
    float* sKP = sm + 64 * 65;       // [64][65], K^T then P
    float* sV  = sm + 2 * 64 * 65;   // [64][65]

    const int bh  = blockIdx.y;
    const int qb  = (gridDim.x - 1) - blockIdx.x;   // heavy tiles first
    const int tid = threadIdx.x;
    const int tx = tid & 15, ty = tid >> 4;

    const float* qp = g_q + (size_t)bh * T_ * HS_;
    const float* kp = g_k + (size_t)bh * T_ * HS_;
    const float* vp = g_v + (size_t)bh * T_ * HS_;

    const int lr  = tid >> 2;        // 0..63 (load row)
    const int lc0 = tid & 3;

    // Load Q tile pre-scaled by 1/sqrt(64)
#pragma unroll
    for (int p = 0; p < 4; p++) {
        int c = (lc0 + 4 * p) * 4;
        float4 v = *reinterpret_cast<const float4*>(qp + (size_t)(qb * 64 + lr) * HS_ + c);
        sQ[lr * 65 + c + 0] = v.x * 0.125f;
        sQ[lr * 65 + c + 1] = v.y * 0.125f;
        sQ[lr * 65 + c + 2] = v.z * 0.125f;
        sQ[lr * 65 + c + 3] = v.w * 0.125f;
    }

    float acc[4][4], mreg[4], lreg[4];
#pragma unroll
    for (int i = 0; i < 4; i++) {
        mreg[i] = -1e30f; lreg[i] = 0.f;
#pragma unroll
        for (int j = 0; j < 4; j++) acc[i][j] = 0.f;
    }

    for (int kb = 0; kb <= qb; kb++) {
        __syncthreads();  // previous tile fully consumed (also guards sQ on iter 0)
        // Load K (transposed) and V tiles
#pragma unroll
        for (int p = 0; p < 4; p++) {
            int c = (lc0 + 4 * p) * 4;
            float4 vk = *reinterpret_cast<const float4*>(kp + (size_t)(kb * 64 + lr) * HS_ + c);
            sKP[(c + 0) * 65 + lr] = vk.x;
            sKP[(c + 1) * 65 + lr] = vk.y;
            sKP[(c + 2) * 65 + lr] = vk.z;
            sKP[(c + 3) * 65 + lr] = vk.w;
            float4 vv = *reinterpret_cast<const float4*>(vp + (size_t)(kb * 64 + lr) * HS_ + c);
            sV[lr * 65 + c + 0] = vv.x;
            sV[lr * 65 + c + 1] = vv.y;
            sV[lr * 65 + c + 2] = vv.z;
            sV[lr * 65 + c + 3] = vv.w;
        }
        __syncthreads();

        // S = (Q*scale) @ K^T
        float s[4][4];
#pragma unroll
        for (int i = 0; i < 4; i++)
#pragma unroll
            for (int j = 0; j < 4; j++) s[i][j] = 0.f;

#pragma unroll 8
        for (int d = 0; d < 64; d++) {
            float a[4], b[4];
#pragma unroll
            for (int i = 0; i < 4; i++) a[i] = sQ[(ty + 16 * i) * 65 + d];
#pragma unroll
            for (int j = 0; j < 4; j++) b[j] = sKP[d * 65 + tx + 16 * j];
#pragma unroll
            for (int i = 0; i < 4; i++)
#pragma unroll
                for (int j = 0; j < 4; j++) s[i][j] = fmaf(a[i], b[j], s[i][j]);
        }

        // Causal mask only on the diagonal tile (tile offsets cancel)
        if (kb == qb) {
#pragma unroll
            for (int i = 0; i < 4; i++)
#pragma unroll
                for (int j = 0; j < 4; j++)
                    if (tx + 16 * j > ty + 16 * i) s[i][j] = -1e30f;
        }

        // Online softmax update (rows live in 16-lane shuffle groups)
        float alpha[4], psum[4];
#pragma unroll
        for (int i = 0; i < 4; i++) {
            float pm = fmaxf(fmaxf(s[i][0], s[i][1]), fmaxf(s[i][2], s[i][3]));
#pragma unroll
            for (int o = 1; o < 16; o <<= 1)
                pm = fmaxf(pm, __shfl_xor_sync(0xffffffffu, pm, o));
            float mnew = fmaxf(mreg[i], pm);
            alpha[i] = __expf(mreg[i] - mnew);
            mreg[i] = mnew;
            float ps = 0.f;
#pragma unroll
            for (int j = 0; j < 4; j++) {
                float pv = __expf(s[i][j] - mnew);
                s[i][j] = pv;
                ps += pv;
            }
#pragma unroll
            for (int o = 1; o < 16; o <<= 1)
                ps += __shfl_xor_sync(0xffffffffu, ps, o);
            psum[i] = ps;
        }
#pragma unroll
        for (int i = 0; i < 4; i++) {
            lreg[i] = lreg[i] * alpha[i] + psum[i];
#pragma unroll
            for (int j = 0; j < 4; j++) acc[i][j] *= alpha[i];
        }

        __syncthreads();   // all K^T reads done before P overwrites the region
#pragma unroll
        for (int i = 0; i < 4; i++)
#pragma unroll
            for (int j = 0; j < 4; j++)
                sKP[(ty + 16 * i) * 65 + tx + 16 * j] = s[i][j];
        __syncthreads();

        // O += P @ V
#pragma unroll 8
        for (int jj = 0; jj < 64; jj++) {
            float a[4], b[4];
#pragma unroll
            for (int i = 0; i < 4; i++) a[i] = sKP[(ty + 16 * i) * 65 + jj];
#pragma unroll
            for (int j = 0; j < 4; j++) b[j] = sV[jj * 65 + tx + 16 * j];
#pragma unroll
            for (int i = 0; i < 4; i++)
#pragma unroll
                for (int j = 0; j < 4; j++) acc[i][j] = fmaf(a[i], b[j], acc[i][j]);
        }
    }

    float* op = g_o + (size_t)bh * T_ * HS_;
#pragma unroll
    for (int i = 0; i < 4; i++) {
        float inv = 1.f / lreg[i];
#pragma unroll
        for (int j = 0; j < 4; j++)
            op[(size_t)(qb * 64 + ty + 16 * i) * HS_ + tx + 16 * j] = acc[i][j] * inv;
    }
}

// ---------------------------------------------------------------------------
// Proj GEMM: Y[8192,768] = gather(g_o as [B,T,H*HS]) @ W_proj[768,768] + b_proj
// ---------------------------------------------------------------------------
__global__ __launch_bounds__(256) void proj_gemm(const float* __restrict__ W,
                                                 const float* __restrict__ bias,
                                                 float* __restrict__ out)
{
    const int N = C_;
    const int K = C_;
    __shared__ float As[128][17];
    __shared__ float Bs[16][128];

    const int tid = threadIdx.x;
    const int tx = tid & 15, ty = tid >> 4;
    const int M0 = blockIdx.y * 128;
    const int N0 = blockIdx.x * 128;

    float acc[8][8];
#pragma unroll
    for (int i = 0; i < 8; i++)
#pragma unroll
        for (int j = 0; j < 8; j++) acc[i][j] = 0.f;

    const int am = tid >> 2;
    const int ak = (tid & 3) * 4;
    const int bk = tid >> 5;
    const int bn = (tid & 31) * 4;

    for (int k0 = 0; k0 < K; k0 += 16) {
#pragma unroll
        for (int r = 0; r < 2; r++) {
            int m = am + r * 64;
            int mg = M0 + m;
            int bi = mg >> 11;
            int t  = mg & (T_ - 1);
            int kc = k0 + ak;
            int h = kc >> 6, hs = kc & 63;   // float4 stays inside one head (4-aligned)
            float4 v = *reinterpret_cast<const float4*>(
                g_o + ((size_t)(bi * H_ + h) * T_ + t) * HS_ + hs);
            As[m][ak + 0] = v.x; As[m][ak + 1] = v.y;
            As[m][ak + 2] = v.z; As[m][ak + 3] = v.w;
        }
#pragma unroll
        for (int r = 0; r < 2; r++) {
            int kk = bk + r * 8;
            *reinterpret_cast<float4*>(&Bs[kk][bn]) =
                *reinterpret_cast<const float4*>(W + (size_t)(k0 + kk) * N + N0 + bn);
        }
        __syncthreads();
#pragma unroll
        for (int kk = 0; kk < 16; kk++) {
            float a[8], b[8];
#pragma unroll
            for (int i = 0; i < 8; i++) a[i] = As[ty + 16 * i][kk];
#pragma unroll
            for (int j = 0; j < 8; j++) b[j] = Bs[kk][tx + 16 * j];
#pragma unroll
            for (int i = 0; i < 8; i++)
#pragma unroll
                for (int j = 0; j < 8; j++) acc[i][j] = fmaf(a[i], b[j], acc[i][j]);
        }
        __syncthreads();
    }

#pragma unroll
    for (int i = 0; i < 8; i++) {
        int mg = M0 + ty + 16 * i;
#pragma unroll
        for (int j = 0; j < 8; j++) {
            int ng = N0 + tx + 16 * j;
            out[(size_t)mg * C_ + ng] = acc[i][j] + bias[ng];
        }
    }
}

// ---------------------------------------------------------------------------
extern "C" void kernel_launch(void* const* d_in, const int* in_sizes, int n_in,
                              void* d_out, int out_size)
{
    const float* x      = (const float*)d_in[0];
    const float* W_attn = (const float*)d_in[1];
    const float* b_attn = (const float*)d_in[2];
    const float* W_proj = (const float*)d_in[3];
    const float* b_proj = (const float*)d_in[4];
    float* out = (float*)d_out;

    cudaFuncSetAttribute(attn_kernel,
                         cudaFuncAttributeMaxDynamicSharedMemorySize, ATT_SMEM);

    qkv_gemm <<<dim3(18, 64), 256>>>(x, W_attn, b_attn);
    attn_kernel<<<dim3(32, 48), 256, ATT_SMEM>>>();
    proj_gemm<<<dim3(6, 64), 256>>>(W_proj, b_proj, out);
}

// round 2
// speedup vs baseline: 1.2287x; 1.2287x over previous
#include <cuda_runtime.h>

#define B_  4
#define T_  2048
#define C_  768
#define H_  12
#define HS_ 64
#define BH_ (B_*H_)

// Scratch (no allocations allowed): Q,K,V,O in [B,H,T,HS] layout
__device__ float g_q[BH_*T_*HS_];   // pre-scaled by 1/sqrt(HS)
__device__ float g_k[BH_*T_*HS_];
__device__ float g_v[BH_*T_*HS_];
__device__ float g_o[BH_*T_*HS_];

// ---------------------------------------------------------------------------
// QKV GEMM: X[8192,768] @ W_attn[768,2304] + b_attn -> scatter to g_q/g_k/g_v
// 128x128 tile, k-chunk 16, 256 threads, 8x8 micro-tile, vector LDS, prefetch.
// ---------------------------------------------------------------------------
__global__ __launch_bounds__(256, 2) void qkv_gemm(const float* __restrict__ X,
                                                   const float* __restrict__ W,
                                                   const float* __restrict__ bias)
{
    const int N = 3 * C_;   // 2304
    const int K = C_;       // 768
    __shared__ float As[16][132];   // k-major, m contiguous (pad 132: STS conflict-free)
    __shared__ float Bs[16][128];   // k-major, n contiguous

    const int tid = threadIdx.x;
    const int tx = tid & 15, ty = tid >> 4;
    const int M0 = blockIdx.y * 128;
    const int N0 = blockIdx.x * 128;

    const int la_m = tid >> 2;          // 0..63 (rows la_m, la_m+64)
    const int la_k = (tid & 3) * 4;     // 0,4,8,12
    const int lb_k = tid >> 5;          // 0..7 (rows lb_k, lb_k+8)
    const int lb_n = (tid & 31) * 4;

    float acc[8][8];
#pragma unroll
    for (int i = 0; i < 8; i++)
#pragma unroll
        for (int j = 0; j < 8; j++) acc[i][j] = 0.f;

    // Prologue: prefetch k0 = 0
    float4 pa0 = *reinterpret_cast<const float4*>(X + (size_t)(M0 + la_m) * K + la_k);
    float4 pa1 = *reinterpret_cast<const float4*>(X + (size_t)(M0 + la_m + 64) * K + la_k);
    float4 pb0 = *reinterpret_cast<const float4*>(W + (size_t)lb_k * N + N0 + lb_n);
    float4 pb1 = *reinterpret_cast<const float4*>(W + (size_t)(lb_k + 8) * N + N0 + lb_n);

    for (int k0 = 0; k0 < K; k0 += 16) {
        // Store prefetched tile (A transposed to k-major)
        As[la_k + 0][la_m] = pa0.x; As[la_k + 1][la_m] = pa0.y;
        As[la_k + 2][la_m] = pa0.z; As[la_k + 3][la_m] = pa0.w;
        As[la_k + 0][la_m + 64] = pa1.x; As[la_k + 1][la_m + 64] = pa1.y;
        As[la_k + 2][la_m + 64] = pa1.z; As[la_k + 3][la_m + 64] = pa1.w;
        *reinterpret_cast<float4*>(&Bs[lb_k][lb_n]) = pb0;
        *reinterpret_cast<float4*>(&Bs[lb_k + 8][lb_n]) = pb1;
        __syncthreads();

        if (k0 + 16 < K) {
            pa0 = *reinterpret_cast<const float4*>(X + (size_t)(M0 + la_m) * K + k0 + 16 + la_k);
            pa1 = *reinterpret_cast<const float4*>(X + (size_t)(M0 + la_m + 64) * K + k0 + 16 + la_k);
            pb0 = *reinterpret_cast<const float4*>(W + (size_t)(k0 + 16 + lb_k) * N + N0 + lb_n);
            pb1 = *reinterpret_cast<const float4*>(W + (size_t)(k0 + 16 + lb_k + 8) * N + N0 + lb_n);
        }

#pragma unroll
        for (int kk = 0; kk < 16; kk++) {
            float4 a0 = *reinterpret_cast<const float4*>(&As[kk][tx * 4]);
            float4 a1 = *reinterpret_cast<const float4*>(&As[kk][tx * 4 + 64]);
            float4 b0 = *reinterpret_cast<const float4*>(&Bs[kk][ty * 4]);
            float4 b1 = *reinterpret_cast<const float4*>(&Bs[kk][ty * 4 + 64]);
            float a[8] = {a0.x, a0.y, a0.z, a0.w, a1.x, a1.y, a1.z, a1.w};
            float b[8] = {b0.x, b0.y, b0.z, b0.w, b1.x, b1.y, b1.z, b1.w};
#pragma unroll
            for (int i = 0; i < 8; i++)
#pragma unroll
                for (int j = 0; j < 8; j++) acc[i][j] = fmaf(a[i], b[j], acc[i][j]);
        }
        __syncthreads();
    }

    // Epilogue: + bias, scatter into [B,H,T,HS]; q pre-scaled by 0.125
#pragma unroll
    for (int i = 0; i < 8; i++) {
        int mg = M0 + (i >> 2) * 64 + tx * 4 + (i & 3);
        int bi = mg >> 11;
        int t  = mg & (T_ - 1);
#pragma unroll
        for (int j = 0; j < 8; j++) {
            int ng = N0 + (j >> 2) * 64 + ty * 4 + (j & 3);
            float val = acc[i][j] + bias[ng];
            int which = ng / C_;       // 0=q,1=k,2=v
            int c = ng - which * C_;
            int h = c >> 6, hs = c & 63;
            if (which == 0) val *= 0.125f;
            float* dst = (which == 0) ? g_q : (which == 1 ? g_k : g_v);
            dst[((size_t)(bi * H_ + h) * T_ + t) * HS_ + hs] = val;
        }
    }
}

// ---------------------------------------------------------------------------
// Flash attention (fp32): block = (b*h, 64-row q tile), 256 threads.
// Contiguous 4x4 micro-tile; Q^T/K^T d-major in smem for vector LDS.
// ---------------------------------------------------------------------------
#define PAD_ 68
#define ATT_SMEM (4 * 64 * PAD_ * 4)

__global__ __launch_bounds__(256) void attn_kernel()
{
    extern __shared__ float sm[];
    float* sQt = sm;                 // [64][PAD_]  Qt[d][m]
    float* sKt = sm + 64 * PAD_;     // [64][PAD_]  Kt[d][n]
    float* sP  = sm + 2 * 64 * PAD_; // [64][PAD_]  P[m][n]
    float* sV  = sm + 3 * 64 * PAD_; // [64][PAD_]  V[n][hs]

    const int bh  = blockIdx.y;
    const int qb  = (gridDim.x - 1) - blockIdx.x;   // heavy tiles first
    const int tid = threadIdx.x;
    const int tx = tid & 15, ty = tid >> 4;

    const float* qp = g_q + (size_t)bh * T_ * HS_;
    const float* kp = g_k + (size_t)bh * T_ * HS_;
    const float* vp = g_v + (size_t)bh * T_ * HS_;

    const int lr = tid >> 2;         // 0..63
    const int lc = (tid & 3) * 4;    // 0,4,8,12 (+16p)

    // Load Q tile transposed (already pre-scaled)
#pragma unroll
    for (int p = 0; p < 4; p++) {
        int c = lc + 16 * p;
        float4 v = *reinterpret_cast<const float4*>(qp + (size_t)(qb * 64 + lr) * HS_ + c);
        sQt[(c + 0) * PAD_ + lr] = v.x;
        sQt[(c + 1) * PAD_ + lr] = v.y;
        sQt[(c + 2) * PAD_ + lr] = v.z;
        sQt[(c + 3) * PAD_ + lr] = v.w;
    }

    float acc[4][4], mreg[4], lreg[4];
#pragma unroll
    for (int i = 0; i < 4; i++) {
        mreg[i] = -1e30f; lreg[i] = 0.f;
#pragma unroll
        for (int j = 0; j < 4; j++) acc[i][j] = 0.f;
    }

    for (int kb = 0; kb <= qb; kb++) {
        __syncthreads();  // previous iteration fully consumed smem
#pragma unroll
        for (int p = 0; p < 4; p++) {
            int c = lc + 16 * p;
            float4 vk = *reinterpret_cast<const float4*>(kp + (size_t)(kb * 64 + lr) * HS_ + c);
            sKt[(c + 0) * PAD_ + lr] = vk.x;
            sKt[(c + 1) * PAD_ + lr] = vk.y;
            sKt[(c + 2) * PAD_ + lr] = vk.z;
            sKt[(c + 3) * PAD_ + lr] = vk.w;
            float4 vv = *reinterpret_cast<const float4*>(vp + (size_t)(kb * 64 + lr) * HS_ + c);
            *reinterpret_cast<float4*>(&sV[lr * PAD_ + c]) = vv;
        }
        __syncthreads();

        // S = Q @ K^T  (rows 4*ty+i, cols 4*tx+j)
        float s[4][4];
#pragma unroll
        for (int i = 0; i < 4; i++)
#pragma unroll
            for (int j = 0; j < 4; j++) s[i][j] = 0.f;

#pragma unroll 16
        for (int d = 0; d < 64; d++) {
            float4 a4 = *reinterpret_cast<const float4*>(&sQt[d * PAD_ + ty * 4]);
            float4 b4 = *reinterpret_cast<const float4*>(&sKt[d * PAD_ + tx * 4]);
            float a[4] = {a4.x, a4.y, a4.z, a4.w};
            float b[4] = {b4.x, b4.y, b4.z, b4.w};
#pragma unroll
            for (int i = 0; i < 4; i++)
#pragma unroll
                for (int j = 0; j < 4; j++) s[i][j] = fmaf(a[i], b[j], s[i][j]);
        }

        // Causal mask on diagonal tile
        if (kb == qb) {
#pragma unroll
            for (int i = 0; i < 4; i++)
#pragma unroll
                for (int j = 0; j < 4; j++)
                    if (tx * 4 + j > ty * 4 + i) s[i][j] = -1e30f;
        }

        // Online softmax (row lives across the 16 tx lanes of a half-warp)
#pragma unroll
        for (int i = 0; i < 4; i++) {
            float pm = fmaxf(fmaxf(s[i][0], s[i][1]), fmaxf(s[i][2], s[i][3]));
#pragma unroll
            for (int o = 1; o < 16; o <<= 1)
                pm = fmaxf(pm, __shfl_xor_sync(0xffffffffu, pm, o));
            float mnew = fmaxf(mreg[i], pm);
            float alpha = __expf(mreg[i] - mnew);
            mreg[i] = mnew;
            float ps = 0.f;
#pragma unroll
            for (int j = 0; j < 4; j++) {
                float pv = __expf(s[i][j] - mnew);
                s[i][j] = pv;
                ps += pv;
            }
#pragma unroll
            for (int o = 1; o < 16; o <<= 1)
                ps += __shfl_xor_sync(0xffffffffu, ps, o);
            lreg[i] = lreg[i] * alpha + ps;
#pragma unroll
            for (int j = 0; j < 4; j++) acc[i][j] *= alpha;
        }

        // Store P (vector store, conflict-free)
#pragma unroll
        for (int i = 0; i < 4; i++) {
            float4 pv = {s[i][0], s[i][1], s[i][2], s[i][3]};
            *reinterpret_cast<float4*>(&sP[(ty * 4 + i) * PAD_ + tx * 4]) = pv;
        }
        __syncthreads();

        // O += P @ V
#pragma unroll 16
        for (int n = 0; n < 64; n++) {
            float4 b4 = *reinterpret_cast<const float4*>(&sV[n * PAD_ + tx * 4]);
            float b[4] = {b4.x, b4.y, b4.z, b4.w};
            float a[4];
#pragma unroll
            for (int i = 0; i < 4; i++) a[i] = sP[(ty * 4 + i) * PAD_ + n];
#pragma unroll
            for (int i = 0; i < 4; i++)
#pragma unroll
                for (int j = 0; j < 4; j++) acc[i][j] = fmaf(a[i], b[j], acc[i][j]);
        }
    }

    float* op = g_o + (size_t)bh * T_ * HS_;
#pragma unroll
    for (int i = 0; i < 4; i++) {
        float inv = 1.f / lreg[i];
        float4 ov = {acc[i][0] * inv, acc[i][1] * inv, acc[i][2] * inv, acc[i][3] * inv};
        *reinterpret_cast<float4*>(op + (size_t)(qb * 64 + ty * 4 + i) * HS_ + tx * 4) = ov;
    }
}

// ---------------------------------------------------------------------------
// Proj GEMM: Y = gather(g_o as [B,T,H*HS]) @ W_proj + b_proj
// ---------------------------------------------------------------------------
__global__ __launch_bounds__(256, 2) void proj_gemm(const float* __restrict__ W,
                                                    const float* __restrict__ bias,
                                                    float* __restrict__ out)
{
    const int N = C_;
    const int K = C_;
    __shared__ float As[16][132];
    __shared__ float Bs[16][128];

    const int tid = threadIdx.x;
    const int tx = tid & 15, ty = tid >> 4;
    const int M0 = blockIdx.y * 128;
    const int N0 = blockIdx.x * 128;

    const int la_m = tid >> 2;
    const int la_k = (tid & 3) * 4;
    const int lb_k = tid >> 5;
    const int lb_n = (tid & 31) * 4;

    float acc[8][8];
#pragma unroll
    for (int i = 0; i < 8; i++)
#pragma unroll
        for (int j = 0; j < 8; j++) acc[i][j] = 0.f;

    auto loadA = [&](int mrow, int k) -> float4 {
        int mg = M0 + mrow;
        int bi = mg >> 11;
        int t  = mg & (T_ - 1);
        int h = k >> 6, hs = k & 63;
        return *reinterpret_cast<const float4*>(
            g_o + ((size_t)(bi * H_ + h) * T_ + t) * HS_ + hs);
    };

    float4 pa0 = loadA(la_m, la_k);
    float4 pa1 = loadA(la_m + 64, la_k);
    float4 pb0 = *reinterpret_cast<const float4*>(W + (size_t)lb_k * N + N0 + lb_n);
    float4 pb1 = *reinterpret_cast<const float4*>(W + (size_t)(lb_k + 8) * N + N0 + lb_n);

    for (int k0 = 0; k0 < K; k0 += 16) {
        As[la_k + 0][la_m] = pa0.x; As[la_k + 1][la_m] = pa0.y;
        As[la_k + 2][la_m] = pa0.z; As[la_k + 3][la_m] = pa0.w;
        As[la_k + 0][la_m + 64] = pa1.x; As[la_k + 1][la_m + 64] = pa1.y;
        As[la_k + 2][la_m + 64] = pa1.z; As[la_k + 3][la_m + 64] = pa1.w;
        *reinterpret_cast<float4*>(&Bs[lb_k][lb_n]) = pb0;
        *reinterpret_cast<float4*>(&Bs[lb_k + 8][lb_n]) = pb1;
        __syncthreads();

        if (k0 + 16 < K) {
            pa0 = loadA(la_m, k0 + 16 + la_k);
            pa1 = loadA(la_m + 64, k0 + 16 + la_k);
            pb0 = *reinterpret_cast<const float4*>(W + (size_t)(k0 + 16 + lb_k) * N + N0 + lb_n);
            pb1 = *reinterpret_cast<const float4*>(W + (size_t)(k0 + 16 + lb_k + 8) * N + N0 + lb_n);
        }

#pragma unroll
        for (int kk = 0; kk < 16; kk++) {
            float4 a0 = *reinterpret_cast<const float4*>(&As[kk][tx * 4]);
            float4 a1 = *reinterpret_cast<const float4*>(&As[kk][tx * 4 + 64]);
            float4 b0 = *reinterpret_cast<const float4*>(&Bs[kk][ty * 4]);
            float4 b1 = *reinterpret_cast<const float4*>(&Bs[kk][ty * 4 + 64]);
            float a[8] = {a0.x, a0.y, a0.z, a0.w, a1.x, a1.y, a1.z, a1.w};
            float b[8] = {b0.x, b0.y, b0.z, b0.w, b1.x, b1.y, b1.z, b1.w};
#pragma unroll
            for (int i = 0; i < 8; i++)
#pragma unroll
                for (int j = 0; j < 8; j++) acc[i][j] = fmaf(a[i], b[j], acc[i][j]);
        }
        __syncthreads();
    }

#pragma unroll
    for (int i = 0; i < 8; i++) {
        int mg = M0 + (i >> 2) * 64 + tx * 4 + (i & 3);
#pragma unroll
        for (int j = 0; j < 8; j++) {
            int ng = N0 + (j >> 2) * 64 + ty * 4 + (j & 3);
            out[(size_t)mg * C_ + ng] = acc[i][j] + bias[ng];
        }
    }
}

// ---------------------------------------------------------------------------
extern "C" void kernel_launch(void* const* d_in, const int* in_sizes, int n_in,
                              void* d_out, int out_size)
{
    const float* x      = (const float*)d_in[0];
    const float* W_attn = (const float*)d_in[1];
    const float* b_attn = (const float*)d_in[2];
    const float* W_proj = (const float*)d_in[3];
    const float* b_proj = (const float*)d_in[4];
    float* out = (float*)d_out;

    cudaFuncSetAttribute(attn_kernel,
                         cudaFuncAttributeMaxDynamicSharedMemorySize, ATT_SMEM);

    qkv_gemm <<<dim3(18, 64), 256>>>(x, W_attn, b_attn);
    attn_kernel<<<dim3(32, 48), 256, ATT_SMEM>>>();
    proj_gemm<<<dim3(6, 64), 256>>>(W_proj, b_proj, out);
}

// round 4
// speedup vs baseline: 1.7674x; 1.4384x over previous
#include <cuda_runtime.h>
#include <cstdint>

#define B_  4
#define T_  2048
#define C_  768
#define H_  12
#define HS_ 64
#define BH_ (B_*H_)

// Scratch (no allocations allowed): Q,K,V,O in [B,H,T,HS] layout
__device__ float g_q[BH_*T_*HS_];   // pre-scaled by 1/sqrt(HS)
__device__ float g_k[BH_*T_*HS_];
__device__ float g_v[BH_*T_*HS_];
__device__ float g_o[BH_*T_*HS_];

// ---------------------------------------------------------------------------
// tf32 mma.sync helpers (baseline PTX, no sm_103a-only features)
// ---------------------------------------------------------------------------
__device__ __forceinline__ uint32_t f2tf32(float x) {
    uint32_t r; asm("cvt.rna.tf32.f32 %0, %1;" : "=r"(r) : "f"(x)); return r;
}
__device__ __forceinline__ void split2(float x, uint32_t& hi, uint32_t& lo) {
    hi = f2tf32(x);
    lo = f2tf32(x - __uint_as_float(hi));
}
__device__ __forceinline__ void mma8(float* d, const uint32_t* a, const uint32_t* b) {
    asm volatile("mma.sync.aligned.m16n8k8.row.col.f32.tf32.tf32.f32 "
        "{%0,%1,%2,%3}, {%4,%5,%6,%7}, {%8,%9}, {%0,%1,%2,%3};"
        : "+f"(d[0]), "+f"(d[1]), "+f"(d[2]), "+f"(d[3])
        : "r"(a[0]), "r"(a[1]), "r"(a[2]), "r"(a[3]), "r"(b[0]), "r"(b[1]));
}

// ---------------------------------------------------------------------------
// GEMM (3xTF32): D = A(128xK) @ W(Kx N-tile 128) + bias
// MODE 0: qkv (A = X, scatter epilogue to g_q/g_k/g_v, q scaled 0.125)
// MODE 1: proj (A = gather g_o, write out)
// smem: per stage Ahi/Alo [128][36], Bhi/Blo [32][136]; double buffered.
// ---------------------------------------------------------------------------
#define AST 36
#define BST 136
#define STAGEF (128*AST*2 + 32*BST*2)   // 17920 floats
#define GEMM_SMEM (2*STAGEF*4)          // 143360 bytes

template<int MODE>
__device__ __forceinline__ void gemm_body(const float* __restrict__ Asrc,
                                          const float* __restrict__ W,
                                          const float* __restrict__ bias,
                                          float* __restrict__ out)
{
    extern __shared__ float sh[];
    const int N = (MODE == 0) ? 3*C_ : C_;
    const int tid = threadIdx.x;
    const int w = tid >> 5, lane = tid & 31;
    const int g = lane >> 2, t = lane & 3;
    const int M0 = blockIdx.y * 128, N0 = blockIdx.x * 128;
    const int mwarp = (w & 3) * 32, nwarp = (w >> 2) * 64;

    float acc[2][8][4];
#pragma unroll
    for (int mt = 0; mt < 2; mt++)
#pragma unroll
        for (int nt = 0; nt < 8; nt++)
#pragma unroll
            for (int r = 0; r < 4; r++) acc[mt][nt][r] = 0.f;

    float4 pa[4], pb[4];
    const int la_r0 = tid >> 3, la_c4 = (tid & 7) * 4;
    const int lb_k0 = tid >> 5, lb_n4 = (tid & 31) * 4;

    auto prefetch = [&](int c) {
        const int k0 = c * 32;
#pragma unroll
        for (int r = 0; r < 4; r++) {
            int row = la_r0 + 32 * r;
            if (MODE == 0) {
                pa[r] = *reinterpret_cast<const float4*>(Asrc + (size_t)(M0 + row) * C_ + k0 + la_c4);
            } else {
                int mg = M0 + row, bi = mg >> 11, tt = mg & (T_ - 1);
                int k = k0 + la_c4, h = k >> 6, hs = k & 63;
                pa[r] = *reinterpret_cast<const float4*>(g_o + ((size_t)(bi*H_ + h)*T_ + tt)*HS_ + hs);
            }
            int kr = lb_k0 + 8 * r;
            pb[r] = *reinterpret_cast<const float4*>(W + (size_t)(k0 + kr) * N + N0 + lb_n4);
        }
    };

    auto stage_sts = [&](int s) {
        float* Ah = sh + s * STAGEF;
        float* Al = Ah + 128 * AST;
        float* Bh = Al + 128 * AST;
        float* Bl = Bh + 32 * BST;
#pragma unroll
        for (int r = 0; r < 4; r++) {
            int row = la_r0 + 32 * r;
            uint4 hi, lo;
            split2(pa[r].x, hi.x, lo.x); split2(pa[r].y, hi.y, lo.y);
            split2(pa[r].z, hi.z, lo.z); split2(pa[r].w, hi.w, lo.w);
            *reinterpret_cast<uint4*>(Ah + row * AST + la_c4) = hi;
            *reinterpret_cast<uint4*>(Al + row * AST + la_c4) = lo;
            int kr = lb_k0 + 8 * r;
            split2(pb[r].x, hi.x, lo.x); split2(pb[r].y, hi.y, lo.y);
            split2(pb[r].z, hi.z, lo.z); split2(pb[r].w, hi.w, lo.w);
            *reinterpret_cast<uint4*>(Bh + kr * BST + lb_n4) = hi;
            *reinterpret_cast<uint4*>(Bl + kr * BST + lb_n4) = lo;
        }
    };

    auto do_mma = [&](int s) {
        const float* Ah = sh + s * STAGEF;
        const float* Al = Ah + 128 * AST;
        const float* Bh = Al + 128 * AST;
        const float* Bl = Bh + 32 * BST;
#pragma unroll
        for (int ks = 0; ks < 4; ks++) {
            uint32_t ah[2][4], al[2][4];
#pragma unroll
            for (int mt = 0; mt < 2; mt++) {
                int base = (mwarp + mt*16 + g) * AST + ks*8 + t;
                ah[mt][0] = __float_as_uint(Ah[base]);
                ah[mt][1] = __float_as_uint(Ah[base + 8*AST]);
                ah[mt][2] = __float_as_uint(Ah[base + 4]);
                ah[mt][3] = __float_as_uint(Ah[base + 8*AST + 4]);
                al[mt][0] = __float_as_uint(Al[base]);
                al[mt][1] = __float_as_uint(Al[base + 8*AST]);
                al[mt][2] = __float_as_uint(Al[base + 4]);
                al[mt][3] = __float_as_uint(Al[base + 8*AST + 4]);
            }
#pragma unroll
            for (int nt = 0; nt < 8; nt++) {
                int bbase = (ks*8 + t) * BST + nwarp + nt*8 + g;
                uint32_t bh[2] = { __float_as_uint(Bh[bbase]), __float_as_uint(Bh[bbase + 4*BST]) };
                uint32_t bl[2] = { __float_as_uint(Bl[bbase]), __float_as_uint(Bl[bbase + 4*BST]) };
#pragma unroll
                for (int mt = 0; mt < 2; mt++) {
                    mma8(acc[mt][nt], ah[mt], bh);
                    mma8(acc[mt][nt], ah[mt], bl);
                    mma8(acc[mt][nt], al[mt], bh);
                }
            }
        }
    };

    prefetch(0);
    stage_sts(0);
    __syncthreads();
    for (int c = 0; c < 24; c++) {
        if (c < 23) prefetch(c + 1);
        do_mma(c & 1);
        if (c < 23) stage_sts((c + 1) & 1);
        __syncthreads();
    }

    // Epilogue (direct from fragments)
    const int which = (MODE == 0) ? (N0 / C_) : 0;
    const float scl = (MODE == 0 && which == 0) ? 0.125f : 1.0f;
    float* dstp = (MODE == 1) ? out : (which == 0 ? g_q : (which == 1 ? g_k : g_v));
#pragma unroll
    for (int mt = 0; mt < 2; mt++) {
#pragma unroll
        for (int nt = 0; nt < 8; nt++) {
            int n_g = N0 + nwarp + nt*8 + 2*t;
            float b0 = bias[n_g], b1 = bias[n_g + 1];
#pragma unroll
            for (int rr = 0; rr < 2; rr++) {
                int m_g = M0 + mwarp + mt*16 + g + rr*8;
                float2 v = { (acc[mt][nt][2*rr] + b0) * scl, (acc[mt][nt][2*rr+1] + b1) * scl };
                if (MODE == 1) {
                    *reinterpret_cast<float2*>(out + (size_t)m_g * C_ + n_g) = v;
                } else {
                    int c = n_g - which * C_;
                    int h = c >> 6, hs = c & 63;
                    int bi = m_g >> 11, tt = m_g & (T_ - 1);
                    *reinterpret_cast<float2*>(dstp + ((size_t)(bi*H_ + h)*T_ + tt)*HS_ + hs) = v;
                }
            }
        }
    }
}

__global__ __launch_bounds__(256, 1) void qkv_tc(const float* __restrict__ X,
                                                 const float* __restrict__ W,
                                                 const float* __restrict__ bias)
{
    gemm_body<0>(X, W, bias, nullptr);
}
__global__ __launch_bounds__(256, 1) void proj_tc(const float* __restrict__ W,
                                                  const float* __restrict__ bias,
                                                  float* __restrict__ out)
{
    gemm_body<1>(nullptr, W, bias, out);
}

// ---------------------------------------------------------------------------
// Flash attention, tf32 mma (3x split), q-tile 128, k-tile 64, 256 threads.
// Warp w owns rows [16w, 16w+16), full 64-col span (softmax stays in-warp).
// smem (floats): QH/QL [128][68], KH/KL [64][68], VH/VL [64][72], PH/PL [128][68]
// ---------------------------------------------------------------------------
#define QH_ 0
#define QL_ 8704
#define KH_ 17408
#define KL_ 21760
#define VH_ 26112
#define VL_ 30720
#define PH_ 35328
#define PL_ 44032
#define ATT_SMEM (52736*4)   // 210944 bytes

__global__ __launch_bounds__(256, 1) void attn_tc()
{
    extern __shared__ float sh[];
    const int bh = blockIdx.y;
    const int qb = (gridDim.x - 1) - blockIdx.x;   // heavy q-tiles first
    const int tid = threadIdx.x;
    const int w = tid >> 5, lane = tid & 31;
    const int g = lane >> 2, t = lane & 3;
    const int m0 = w * 16;

    const float* qp = g_q + (size_t)bh * T_ * HS_;
    const float* kp = g_k + (size_t)bh * T_ * HS_;
    const float* vp = g_v + (size_t)bh * T_ * HS_;

    // Load + split Q tile [128][64] (pre-scaled at qkv epilogue)
    {
        const int r0 = tid >> 4, c4 = (tid & 15) * 4;
#pragma unroll
        for (int r = 0; r < 8; r++) {
            int row = r0 + 16 * r;
            float4 v = *reinterpret_cast<const float4*>(qp + (size_t)(qb*128 + row)*HS_ + c4);
            uint4 hi, lo;
            split2(v.x, hi.x, lo.x); split2(v.y, hi.y, lo.y);
            split2(v.z, hi.z, lo.z); split2(v.w, hi.w, lo.w);
            *reinterpret_cast<uint4*>(sh + QH_ + row*68 + c4) = hi;
            *reinterpret_cast<uint4*>(sh + QL_ + row*68 + c4) = lo;
        }
    }

    float o[8][4];
#pragma unroll
    for (int nt = 0; nt < 8; nt++)
#pragma unroll
        for (int r = 0; r < 4; r++) o[nt][r] = 0.f;
    float mrow[2] = { -1e30f, -1e30f };
    float lrow[2] = { 0.f, 0.f };

    const int nkb = 2 * qb + 2;
    for (int kb = 0; kb < nkb; kb++) {
        __syncthreads();   // previous PV reads of sK/sV/sP done (also guards Q on kb=0)
        // Load + split K,V tiles [64][64]
        {
            const int r0 = tid >> 4, c4 = (tid & 15) * 4;
#pragma unroll
            for (int r = 0; r < 4; r++) {
                int row = r0 + 16 * r;
                float4 vk = *reinterpret_cast<const float4*>(kp + (size_t)(kb*64 + row)*HS_ + c4);
                uint4 hi, lo;
                split2(vk.x, hi.x, lo.x); split2(vk.y, hi.y, lo.y);
                split2(vk.z, hi.z, lo.z); split2(vk.w, hi.w, lo.w);
                *reinterpret_cast<uint4*>(sh + KH_ + row*68 + c4) = hi;
                *reinterpret_cast<uint4*>(sh + KL_ + row*68 + c4) = lo;
                float4 vv = *reinterpret_cast<const float4*>(vp + (size_t)(kb*64 + row)*HS_ + c4);
                split2(vv.x, hi.x, lo.x); split2(vv.y, hi.y, lo.y);
                split2(vv.z, hi.z, lo.z); split2(vv.w, hi.w, lo.w);
                *reinterpret_cast<uint4*>(sh + VH_ + row*72 + c4) = hi;
                *reinterpret_cast<uint4*>(sh + VL_ + row*72 + c4) = lo;
            }
        }
        __syncthreads();

        // ---- S = Q @ K^T  (warp: rows m0..m0+15, cols 0..63) ----
        float s[8][4];
#pragma unroll
        for (int nt = 0; nt < 8; nt++)
#pragma unroll
            for (int r = 0; r < 4; r++) s[nt][r] = 0.f;

#pragma unroll
        for (int ks = 0; ks < 8; ks++) {
            int abase = (m0 + g)*68 + ks*8 + t;
            uint32_t qh[4], ql[4];
            qh[0] = __float_as_uint(sh[QH_ + abase]);
            qh[1] = __float_as_uint(sh[QH_ + abase + 8*68]);
            qh[2] = __float_as_uint(sh[QH_ + abase + 4]);
            qh[3] = __float_as_uint(sh[QH_ + abase + 8*68 + 4]);
            ql[0] = __float_as_uint(sh[QL_ + abase]);
            ql[1] = __float_as_uint(sh[QL_ + abase + 8*68]);
            ql[2] = __float_as_uint(sh[QL_ + abase + 4]);
            ql[3] = __float_as_uint(sh[QL_ + abase + 8*68 + 4]);
#pragma unroll
            for (int nt = 0; nt < 8; nt++) {
                int bbase = (nt*8 + g)*68 + ks*8 + t;   // K[tok][d]
                uint32_t bh2[2] = { __float_as_uint(sh[KH_ + bbase]), __float_as_uint(sh[KH_ + bbase + 4]) };
                uint32_t bl2[2] = { __float_as_uint(sh[KL_ + bbase]), __float_as_uint(sh[KL_ + bbase + 4]) };
                mma8(s[nt], qh, bh2);
                mma8(s[nt], qh, bl2);
                mma8(s[nt], ql, bh2);
            }
        }

        // Causal mask (only possible on the two diagonal-adjacent k-tiles)
        if (kb >= 2*qb) {
            int qr0 = qb*128 + m0 + g;
#pragma unroll
            for (int nt = 0; nt < 8; nt++) {
                int col = kb*64 + nt*8 + 2*t;
                if (col > qr0)     s[nt][0] = -1e30f;
                if (col+1 > qr0)   s[nt][1] = -1e30f;
                if (col > qr0+8)   s[nt][2] = -1e30f;
                if (col+1 > qr0+8) s[nt][3] = -1e30f;
            }
        }

        // ---- online softmax (rows g, g+8 live in 4-lane shuffle groups) ----
        float pm0 = -1e30f, pm1 = -1e30f;
#pragma unroll
        for (int nt = 0; nt < 8; nt++) {
            pm0 = fmaxf(pm0, fmaxf(s[nt][0], s[nt][1]));
            pm1 = fmaxf(pm1, fmaxf(s[nt][2], s[nt][3]));
        }
        pm0 = fmaxf(pm0, __shfl_xor_sync(0xffffffffu, pm0, 1));
        pm0 = fmaxf(pm0, __shfl_xor_sync(0xffffffffu, pm0, 2));
        pm1 = fmaxf(pm1, __shfl_xor_sync(0xffffffffu, pm1, 1));
        pm1 = fmaxf(pm1, __shfl_xor_sync(0xffffffffu, pm1, 2));
        float mn0 = fmaxf(mrow[0], pm0), mn1 = fmaxf(mrow[1], pm1);
        float al0 = __expf(mrow[0] - mn0), al1 = __expf(mrow[1] - mn1);
        mrow[0] = mn0; mrow[1] = mn1;
        float sum0 = 0.f, sum1 = 0.f;
#pragma unroll
        for (int nt = 0; nt < 8; nt++) {
            s[nt][0] = __expf(s[nt][0] - mn0); sum0 += s[nt][0];
            s[nt][1] = __expf(s[nt][1] - mn0); sum0 += s[nt][1];
            s[nt][2] = __expf(s[nt][2] - mn1); sum1 += s[nt][2];
            s[nt][3] = __expf(s[nt][3] - mn1); sum1 += s[nt][3];
        }
        sum0 += __shfl_xor_sync(0xffffffffu, sum0, 1);
        sum0 += __shfl_xor_sync(0xffffffffu, sum0, 2);
        sum1 += __shfl_xor_sync(0xffffffffu, sum1, 1);
        sum1 += __shfl_xor_sync(0xffffffffu, sum1, 2);
        lrow[0] = lrow[0] * al0 + sum0;
        lrow[1] = lrow[1] * al1 + sum1;
#pragma unroll
        for (int nt = 0; nt < 8; nt++) {
            o[nt][0] *= al0; o[nt][1] *= al0;
            o[nt][2] *= al1; o[nt][3] *= al1;
        }

        // ---- stage P (split) to smem ----
#pragma unroll
        for (int nt = 0; nt < 8; nt++) {
            int col = nt*8 + 2*t;
            uint32_t hi, lo;
            split2(s[nt][0], hi, lo);
            sh[PH_ + (m0+g)*68 + col]     = __uint_as_float(hi);
            sh[PL_ + (m0+g)*68 + col]     = __uint_as_float(lo);
            split2(s[nt][1], hi, lo);
            sh[PH_ + (m0+g)*68 + col+1]   = __uint_as_float(hi);
            sh[PL_ + (m0+g)*68 + col+1]   = __uint_as_float(lo);
            split2(s[nt][2], hi, lo);
            sh[PH_ + (m0+g+8)*68 + col]   = __uint_as_float(hi);
            sh[PL_ + (m0+g+8)*68 + col]   = __uint_as_float(lo);
            split2(s[nt][3], hi, lo);
            sh[PH_ + (m0+g+8)*68 + col+1] = __uint_as_float(hi);
            sh[PL_ + (m0+g+8)*68 + col+1] = __uint_as_float(lo);
        }
        __syncthreads();

        // ---- O += P @ V ----
#pragma unroll
        for (int ks = 0; ks < 8; ks++) {
            int abase = (m0 + g)*68 + ks*8 + t;
            uint32_t ph[4], pl[4];
            ph[0] = __float_as_uint(sh[PH_ + abase]);
            ph[1] = __float_as_uint(sh[PH_ + abase + 8*68]);
            ph[2] = __float_as_uint(sh[PH_ + abase + 4]);
            ph[3] = __float_as_uint(sh[PH_ + abase + 8*68 + 4]);
            pl[0] = __float_as_uint(sh[PL_ + abase]);
            pl[1] = __float_as_uint(sh[PL_ + abase + 8*68]);
            pl[2] = __float_as_uint(sh[PL_ + abase + 4]);
            pl[3] = __float_as_uint(sh[PL_ + abase + 8*68 + 4]);
#pragma unroll
            for (int nt = 0; nt < 8; nt++) {
                int b0 = (ks*8 + t)*72 + nt*8 + g;     // V[tok][d]
                int b1 = (ks*8 + t + 4)*72 + nt*8 + g;
                uint32_t vh2[2] = { __float_as_uint(sh[VH_ + b0]), __float_as_uint(sh[VH_ + b1]) };
                uint32_t vl2[2] = { __float_as_uint(sh[VL_ + b0]), __float_as_uint(sh[VL_ + b1]) };
                mma8(o[nt], ph, vh2);
                mma8(o[nt], ph, vl2);
                mma8(o[nt], pl, vh2);
            }
        }
    }

    // ---- write O / l ----
    float inv0 = 1.f / lrow[0], inv1 = 1.f / lrow[1];
    float* op = g_o + (size_t)bh * T_ * HS_;
#pragma unroll
    for (int nt = 0; nt < 8; nt++) {
        int d = nt*8 + 2*t;
        int r0 = qb*128 + m0 + g;
        float2 v0 = { o[nt][0] * inv0, o[nt][1] * inv0 };
        float2 v1 = { o[nt][2] * inv1, o[nt][3] * inv1 };
        *reinterpret_cast<float2*>(op + (size_t)r0 * HS_ + d)       = v0;
        *reinterpret_cast<float2*>(op + (size_t)(r0 + 8) * HS_ + d) = v1;
    }
}

// ---------------------------------------------------------------------------
extern "C" void kernel_launch(void* const* d_in, const int* in_sizes, int n_in,
                              void* d_out, int out_size)
{
    const float* x      = (const float*)d_in[0];
    const float* W_attn = (const float*)d_in[1];
    const float* b_attn = (const float*)d_in[2];
    const float* W_proj = (const float*)d_in[3];
    const float* b_proj = (const float*)d_in[4];
    float* out = (float*)d_out;

    cudaFuncSetAttribute(qkv_tc,  cudaFuncAttributeMaxDynamicSharedMemorySize, GEMM_SMEM);
    cudaFuncSetAttribute(proj_tc, cudaFuncAttributeMaxDynamicSharedMemorySize, GEMM_SMEM);
    cudaFuncSetAttribute(attn_tc, cudaFuncAttributeMaxDynamicSharedMemorySize, ATT_SMEM);

    qkv_tc <<<dim3(18, 64), 256, GEMM_SMEM>>>(x, W_attn, b_attn);
    attn_tc<<<dim3(16, 48), 256, ATT_SMEM>>>();
    proj_tc<<<dim3(6, 64), 256, GEMM_SMEM>>>(W_proj, b_proj, out);
}

// round 5
// speedup vs baseline: 1.7702x; 1.0016x over previous
#include <cuda_runtime.h>
#include <cstdint>

#define B_  4
#define T_  2048
#define C_  768
#define H_  12
#define HS_ 64
#define BH_ (B_*H_)

// Scratch (no allocations allowed): Q,K,V,O in [B,H,T,HS] layout
__device__ float g_q[BH_*T_*HS_];   // pre-scaled by 1/sqrt(HS)
__device__ float g_k[BH_*T_*HS_];
__device__ float g_v[BH_*T_*HS_];
__device__ float g_o[BH_*T_*HS_];

// ---------------------------------------------------------------------------
// tf32 mma.sync helpers (baseline PTX, no sm_103a-only features)
// ---------------------------------------------------------------------------
__device__ __forceinline__ uint32_t f2tf32(float x) {
    uint32_t r; asm("cvt.rna.tf32.f32 %0, %1;" : "=r"(r) : "f"(x)); return r;
}
__device__ __forceinline__ void split2(float x, uint32_t& hi, uint32_t& lo) {
    hi = f2tf32(x);
    lo = f2tf32(x - __uint_as_float(hi));
}
__device__ __forceinline__ void mma8(float* d, const uint32_t* a, const uint32_t* b) {
    asm volatile("mma.sync.aligned.m16n8k8.row.col.f32.tf32.tf32.f32 "
        "{%0,%1,%2,%3}, {%4,%5,%6,%7}, {%8,%9}, {%0,%1,%2,%3};"
        : "+f"(d[0]), "+f"(d[1]), "+f"(d[2]), "+f"(d[3])
        : "r"(a[0]), "r"(a[1]), "r"(a[2]), "r"(a[3]), "r"(b[0]), "r"(b[1]));
}

// ---------------------------------------------------------------------------
// GEMM (3xTF32): D = A(128xK) @ W(Kx N-tile 128) + bias
// MODE 0: qkv (A = X, scatter epilogue to g_q/g_k/g_v, q scaled 0.125)
// MODE 1: proj (A = gather g_o, write out)
// smem: per stage Ahi/Alo [128][36], Bhi/Blo [32][136]; double buffered.
// ---------------------------------------------------------------------------
#define AST 36
#define BST 136
#define STAGEF (128*AST*2 + 32*BST*2)   // 17920 floats
#define GEMM_SMEM (2*STAGEF*4)          // 143360 bytes

template<int MODE>
__device__ __forceinline__ void gemm_body(const float* __restrict__ Asrc,
                                          const float* __restrict__ W,
                                          const float* __restrict__ bias,
                                          float* __restrict__ out)
{
    extern __shared__ float sh[];
    const int N = (MODE == 0) ? 3*C_ : C_;
    const int tid = threadIdx.x;
    const int w = tid >> 5, lane = tid & 31;
    const int g = lane >> 2, t = lane & 3;
    const int M0 = blockIdx.y * 128, N0 = blockIdx.x * 128;
    const int mwarp = (w & 3) * 32, nwarp = (w >> 2) * 64;

    float acc[2][8][4];
#pragma unroll
    for (int mt = 0; mt < 2; mt++)
#pragma unroll
        for (int nt = 0; nt < 8; nt++)
#pragma unroll
            for (int r = 0; r < 4; r++) acc[mt][nt][r] = 0.f;

    float4 pa[4], pb[4];
    const int la_r0 = tid >> 3, la_c4 = (tid & 7) * 4;
    const int lb_k0 = tid >> 5, lb_n4 = (tid & 31) * 4;

    auto prefetch = [&](int c) {
        const int k0 = c * 32;
#pragma unroll
        for (int r = 0; r < 4; r++) {
            int row = la_r0 + 32 * r;
            if (MODE == 0) {
                pa[r] = *reinterpret_cast<const float4*>(Asrc + (size_t)(M0 + row) * C_ + k0 + la_c4);
            } else {
                int mg = M0 + row, bi = mg >> 11, tt = mg & (T_ - 1);
                int k = k0 + la_c4, h = k >> 6, hs = k & 63;
                pa[r] = *reinterpret_cast<const float4*>(g_o + ((size_t)(bi*H_ + h)*T_ + tt)*HS_ + hs);
            }
            int kr = lb_k0 + 8 * r;
            pb[r] = *reinterpret_cast<const float4*>(W + (size_t)(k0 + kr) * N + N0 + lb_n4);
        }
    };

    auto stage_sts = [&](int s) {
        float* Ah = sh + s * STAGEF;
        float* Al = Ah + 128 * AST;
        float* Bh = Al + 128 * AST;
        float* Bl = Bh + 32 * BST;
#pragma unroll
        for (int r = 0; r < 4; r++) {
            int row = la_r0 + 32 * r;
            uint4 hi, lo;
            split2(pa[r].x, hi.x, lo.x); split2(pa[r].y, hi.y, lo.y);
            split2(pa[r].z, hi.z, lo.z); split2(pa[r].w, hi.w, lo.w);
            *reinterpret_cast<uint4*>(Ah + row * AST + la_c4) = hi;
            *reinterpret_cast<uint4*>(Al + row * AST + la_c4) = lo;
            int kr = lb_k0 + 8 * r;
            split2(pb[r].x, hi.x, lo.x); split2(pb[r].y, hi.y, lo.y);
            split2(pb[r].z, hi.z, lo.z); split2(pb[r].w, hi.w, lo.w);
            *reinterpret_cast<uint4*>(Bh + kr * BST + lb_n4) = hi;
            *reinterpret_cast<uint4*>(Bl + kr * BST + lb_n4) = lo;
        }
    };

    auto do_mma = [&](int s) {
        const float* Ah = sh + s * STAGEF;
        const float* Al = Ah + 128 * AST;
        const float* Bh = Al + 128 * AST;
        const float* Bl = Bh + 32 * BST;
#pragma unroll
        for (int ks = 0; ks < 4; ks++) {
            uint32_t ah[2][4], al[2][4];
#pragma unroll
            for (int mt = 0; mt < 2; mt++) {
                int base = (mwarp + mt*16 + g) * AST + ks*8 + t;
                ah[mt][0] = __float_as_uint(Ah[base]);
                ah[mt][1] = __float_as_uint(Ah[base + 8*AST]);
                ah[mt][2] = __float_as_uint(Ah[base + 4]);
                ah[mt][3] = __float_as_uint(Ah[base + 8*AST + 4]);
                al[mt][0] = __float_as_uint(Al[base]);
                al[mt][1] = __float_as_uint(Al[base + 8*AST]);
                al[mt][2] = __float_as_uint(Al[base + 4]);
                al[mt][3] = __float_as_uint(Al[base + 8*AST + 4]);
            }
#pragma unroll
            for (int nt = 0; nt < 8; nt++) {
                int bbase = (ks*8 + t) * BST + nwarp + nt*8 + g;
                uint32_t bh[2] = { __float_as_uint(Bh[bbase]), __float_as_uint(Bh[bbase + 4*BST]) };
                uint32_t bl[2] = { __float_as_uint(Bl[bbase]), __float_as_uint(Bl[bbase + 4*BST]) };
#pragma unroll
                for (int mt = 0; mt < 2; mt++) {
                    mma8(acc[mt][nt], ah[mt], bh);
                    mma8(acc[mt][nt], ah[mt], bl);
                    mma8(acc[mt][nt], al[mt], bh);
                }
            }
        }
    };

    prefetch(0);
    stage_sts(0);
    __syncthreads();
    for (int c = 0; c < 24; c++) {
        if (c < 23) prefetch(c + 1);
        do_mma(c & 1);
        if (c < 23) stage_sts((c + 1) & 1);
        __syncthreads();
    }

    // Epilogue (direct from fragments)
    const int which = (MODE == 0) ? (N0 / C_) : 0;
    const float scl = (MODE == 0 && which == 0) ? 0.125f : 1.0f;
    float* dstp = (MODE == 1) ? out : (which == 0 ? g_q : (which == 1 ? g_k : g_v));
#pragma unroll
    for (int mt = 0; mt < 2; mt++) {
#pragma unroll
        for (int nt = 0; nt < 8; nt++) {
            int n_g = N0 + nwarp + nt*8 + 2*t;
            float b0 = bias[n_g], b1 = bias[n_g + 1];
#pragma unroll
            for (int rr = 0; rr < 2; rr++) {
                int m_g = M0 + mwarp + mt*16 + g + rr*8;
                float2 v = { (acc[mt][nt][2*rr] + b0) * scl, (acc[mt][nt][2*rr+1] + b1) * scl };
                if (MODE == 1) {
                    *reinterpret_cast<float2*>(out + (size_t)m_g * C_ + n_g) = v;
                } else {
                    int c = n_g - which * C_;
                    int h = c >> 6, hs = c & 63;
                    int bi = m_g >> 11, tt = m_g & (T_ - 1);
                    *reinterpret_cast<float2*>(dstp + ((size_t)(bi*H_ + h)*T_ + tt)*HS_ + hs) = v;
                }
            }
        }
    }
}

__global__ __launch_bounds__(256, 1) void qkv_tc(const float* __restrict__ X,
                                                 const float* __restrict__ W,
                                                 const float* __restrict__ bias)
{
    gemm_body<0>(X, W, bias, nullptr);
}
__global__ __launch_bounds__(256, 1) void proj_tc(const float* __restrict__ W,
                                                  const float* __restrict__ bias,
                                                  float* __restrict__ out)
{
    gemm_body<1>(nullptr, W, bias, out);
}

// ---------------------------------------------------------------------------
// Flash attention, tf32 mma (3x split), q-tile 128, k-tile 64, 256 threads.
// Warp w owns rows [16w, 16w+16), full 64-col span (softmax stays in-warp).
// smem (floats): QH/QL [128][68], KH/KL [64][68], VH/VL [64][72], PH/PL [128][68]
// ---------------------------------------------------------------------------
#define QH_ 0
#define QL_ 8704
#define KH_ 17408
#define KL_ 21760
#define VH_ 26112
#define VL_ 30720
#define PH_ 35328
#define PL_ 44032
#define ATT_SMEM (52736*4)   // 210944 bytes

__global__ __launch_bounds__(256, 1) void attn_tc()
{
    extern __shared__ float sh[];
    const int bh = blockIdx.y;
    const int qb = (gridDim.x - 1) - blockIdx.x;   // heavy q-tiles first
    const int tid = threadIdx.x;
    const int w = tid >> 5, lane = tid & 31;
    const int g = lane >> 2, t = lane & 3;
    const int m0 = w * 16;

    const float* qp = g_q + (size_t)bh * T_ * HS_;
    const float* kp = g_k + (size_t)bh * T_ * HS_;
    const float* vp = g_v + (size_t)bh * T_ * HS_;

    // Load + split Q tile [128][64] (pre-scaled at qkv epilogue)
    {
        const int r0 = tid >> 4, c4 = (tid & 15) * 4;
#pragma unroll
        for (int r = 0; r < 8; r++) {
            int row = r0 + 16 * r;
            float4 v = *reinterpret_cast<const float4*>(qp + (size_t)(qb*128 + row)*HS_ + c4);
            uint4 hi, lo;
            split2(v.x, hi.x, lo.x); split2(v.y, hi.y, lo.y);
            split2(v.z, hi.z, lo.z); split2(v.w, hi.w, lo.w);
            *reinterpret_cast<uint4*>(sh + QH_ + row*68 + c4) = hi;
            *reinterpret_cast<uint4*>(sh + QL_ + row*68 + c4) = lo;
        }
    }

    float o[8][4];
#pragma unroll
    for (int nt = 0; nt < 8; nt++)
#pragma unroll
        for (int r = 0; r < 4; r++) o[nt][r] = 0.f;
    float mrow[2] = { -1e30f, -1e30f };
    float lrow[2] = { 0.f, 0.f };

    const int nkb = 2 * qb + 2;
    for (int kb = 0; kb < nkb; kb++) {
        __syncthreads();   // previous PV reads of sK/sV/sP done (also guards Q on kb=0)
        // Load + split K,V tiles [64][64]
        {
            const int r0 = tid >> 4, c4 = (tid & 15) * 4;
#pragma unroll
            for (int r = 0; r < 4; r++) {
                int row = r0 + 16 * r;
                float4 vk = *reinterpret_cast<const float4*>(kp + (size_t)(kb*64 + row)*HS_ + c4);
                uint4 hi, lo;
                split2(vk.x, hi.x, lo.x); split2(vk.y, hi.y, lo.y);
                split2(vk.z, hi.z, lo.z); split2(vk.w, hi.w, lo.w);
                *reinterpret_cast<uint4*>(sh + KH_ + row*68 + c4) = hi;
                *reinterpret_cast<uint4*>(sh + KL_ + row*68 + c4) = lo;
                float4 vv = *reinterpret_cast<const float4*>(vp + (size_t)(kb*64 + row)*HS_ + c4);
                split2(vv.x, hi.x, lo.x); split2(vv.y, hi.y, lo.y);
                split2(vv.z, hi.z, lo.z); split2(vv.w, hi.w, lo.w);
                *reinterpret_cast<uint4*>(sh + VH_ + row*72 + c4) = hi;
                *reinterpret_cast<uint4*>(sh + VL_ + row*72 + c4) = lo;
            }
        }
        __syncthreads();

        // ---- S = Q @ K^T  (warp: rows m0..m0+15, cols 0..63) ----
        float s[8][4];
#pragma unroll
        for (int nt = 0; nt < 8; nt++)
#pragma unroll
            for (int r = 0; r < 4; r++) s[nt][r] = 0.f;

#pragma unroll
        for (int ks = 0; ks < 8; ks++) {
            int abase = (m0 + g)*68 + ks*8 + t;
            uint32_t qh[4], ql[4];
            qh[0] = __float_as_uint(sh[QH_ + abase]);
            qh[1] = __float_as_uint(sh[QH_ + abase + 8*68]);
            qh[2] = __float_as_uint(sh[QH_ + abase + 4]);
            qh[3] = __float_as_uint(sh[QH_ + abase + 8*68 + 4]);
            ql[0] = __float_as_uint(sh[QL_ + abase]);
            ql[1] = __float_as_uint(sh[QL_ + abase + 8*68]);
            ql[2] = __float_as_uint(sh[QL_ + abase + 4]);
            ql[3] = __float_as_uint(sh[QL_ + abase + 8*68 + 4]);
#pragma unroll
            for (int nt = 0; nt < 8; nt++) {
                int bbase = (nt*8 + g)*68 + ks*8 + t;   // K[tok][d]
                uint32_t bh2[2] = { __float_as_uint(sh[KH_ + bbase]), __float_as_uint(sh[KH_ + bbase + 4]) };
                uint32_t bl2[2] = { __float_as_uint(sh[KL_ + bbase]), __float_as_uint(sh[KL_ + bbase + 4]) };
                mma8(s[nt], qh, bh2);
                mma8(s[nt], qh, bl2);
                mma8(s[nt], ql, bh2);
            }
        }

        // Causal mask (only possible on the two diagonal-adjacent k-tiles)
        if (kb >= 2*qb) {
            int qr0 = qb*128 + m0 + g;
#pragma unroll
            for (int nt = 0; nt < 8; nt++) {
                int col = kb*64 + nt*8 + 2*t;
                if (col > qr0)     s[nt][0] = -1e30f;
                if (col+1 > qr0)   s[nt][1] = -1e30f;
                if (col > qr0+8)   s[nt][2] = -1e30f;
                if (col+1 > qr0+8) s[nt][3] = -1e30f;
            }
        }

        // ---- online softmax (rows g, g+8 live in 4-lane shuffle groups) ----
        float pm0 = -1e30f, pm1 = -1e30f;
#pragma unroll
        for (int nt = 0; nt < 8; nt++) {
            pm0 = fmaxf(pm0, fmaxf(s[nt][0], s[nt][1]));
            pm1 = fmaxf(pm1, fmaxf(s[nt][2], s[nt][3]));
        }
        pm0 = fmaxf(pm0, __shfl_xor_sync(0xffffffffu, pm0, 1));
        pm0 = fmaxf(pm0, __shfl_xor_sync(0xffffffffu, pm0, 2));
        pm1 = fmaxf(pm1, __shfl_xor_sync(0xffffffffu, pm1, 1));
        pm1 = fmaxf(pm1, __shfl_xor_sync(0xffffffffu, pm1, 2));
        float mn0 = fmaxf(mrow[0], pm0), mn1 = fmaxf(mrow[1], pm1);
        float al0 = __expf(mrow[0] - mn0), al1 = __expf(mrow[1] - mn1);
        mrow[0] = mn0; mrow[1] = mn1;
        float sum0 = 0.f, sum1 = 0.f;
#pragma unroll
        for (int nt = 0; nt < 8; nt++) {
            s[nt][0] = __expf(s[nt][0] - mn0); sum0 += s[nt][0];
            s[nt][1] = __expf(s[nt][1] - mn0); sum0 += s[nt][1];
            s[nt][2] = __expf(s[nt][2] - mn1); sum1 += s[nt][2];
            s[nt][3] = __expf(s[nt][3] - mn1); sum1 += s[nt][3];
        }
        sum0 += __shfl_xor_sync(0xffffffffu, sum0, 1);
        sum0 += __shfl_xor_sync(0xffffffffu, sum0, 2);
        sum1 += __shfl_xor_sync(0xffffffffu, sum1, 1);
        sum1 += __shfl_xor_sync(0xffffffffu, sum1, 2);
        lrow[0] = lrow[0] * al0 + sum0;
        lrow[1] = lrow[1] * al1 + sum1;
#pragma unroll
        for (int nt = 0; nt < 8; nt++) {
            o[nt][0] *= al0; o[nt][1] *= al0;
            o[nt][2] *= al1; o[nt][3] *= al1;
        }

        // ---- stage P (split) to smem ----
#pragma unroll
        for (int nt = 0; nt < 8; nt++) {
            int col = nt*8 + 2*t;
            uint32_t hi, lo;
            split2(s[nt][0], hi, lo);
            sh[PH_ + (m0+g)*68 + col]     = __uint_as_float(hi);
            sh[PL_ + (m0+g)*68 + col]     = __uint_as_float(lo);
            split2(s[nt][1], hi, lo);
            sh[PH_ + (m0+g)*68 + col+1]   = __uint_as_float(hi);
            sh[PL_ + (m0+g)*68 + col+1]   = __uint_as_float(lo);
            split2(s[nt][2], hi, lo);
            sh[PH_ + (m0+g+8)*68 + col]   = __uint_as_float(hi);
            sh[PL_ + (m0+g+8)*68 + col]   = __uint_as_float(lo);
            split2(s[nt][3], hi, lo);
            sh[PH_ + (m0+g+8)*68 + col+1] = __uint_as_float(hi);
            sh[PL_ + (m0+g+8)*68 + col+1] = __uint_as_float(lo);
        }
        __syncthreads();

        // ---- O += P @ V ----
#pragma unroll
        for (int ks = 0; ks < 8; ks++) {
            int abase = (m0 + g)*68 + ks*8 + t;
            uint32_t ph[4], pl[4];
            ph[0] = __float_as_uint(sh[PH_ + abase]);
            ph[1] = __float_as_uint(sh[PH_ + abase + 8*68]);
            ph[2] = __float_as_uint(sh[PH_ + abase + 4]);
            ph[3] = __float_as_uint(sh[PH_ + abase + 8*68 + 4]);
            pl[0] = __float_as_uint(sh[PL_ + abase]);
            pl[1] = __float_as_uint(sh[PL_ + abase + 8*68]);
            pl[2] = __float_as_uint(sh[PL_ + abase + 4]);
            pl[3] = __float_as_uint(sh[PL_ + abase + 8*68 + 4]);
#pragma unroll
            for (int nt = 0; nt < 8; nt++) {
                int b0 = (ks*8 + t)*72 + nt*8 + g;     // V[tok][d]
                int b1 = (ks*8 + t + 4)*72 + nt*8 + g;
                uint32_t vh2[2] = { __float_as_uint(sh[VH_ + b0]), __float_as_uint(sh[VH_ + b1]) };
                uint32_t vl2[2] = { __float_as_uint(sh[VL_ + b0]), __float_as_uint(sh[VL_ + b1]) };
                mma8(o[nt], ph, vh2);
                mma8(o[nt], ph, vl2);
                mma8(o[nt], pl, vh2);
            }
        }
    }

    // ---- write O / l ----
    float inv0 = 1.f / lrow[0], inv1 = 1.f / lrow[1];
    float* op = g_o + (size_t)bh * T_ * HS_;
#pragma unroll
    for (int nt = 0; nt < 8; nt++) {
        int d = nt*8 + 2*t;
        int r0 = qb*128 + m0 + g;
        float2 v0 = { o[nt][0] * inv0, o[nt][1] * inv0 };
        float2 v1 = { o[nt][2] * inv1, o[nt][3] * inv1 };
        *reinterpret_cast<float2*>(op + (size_t)r0 * HS_ + d)       = v0;
        *reinterpret_cast<float2*>(op + (size_t)(r0 + 8) * HS_ + d) = v1;
    }
}

// ---------------------------------------------------------------------------
extern "C" void kernel_launch(void* const* d_in, const int* in_sizes, int n_in,
                              void* d_out, int out_size)
{
    const float* x      = (const float*)d_in[0];
    const float* W_attn = (const float*)d_in[1];
    const float* b_attn = (const float*)d_in[2];
    const float* W_proj = (const float*)d_in[3];
    const float* b_proj = (const float*)d_in[4];
    float* out = (float*)d_out;

    cudaFuncSetAttribute(qkv_tc,  cudaFuncAttributeMaxDynamicSharedMemorySize, GEMM_SMEM);
    cudaFuncSetAttribute(proj_tc, cudaFuncAttributeMaxDynamicSharedMemorySize, GEMM_SMEM);
    cudaFuncSetAttribute(attn_tc, cudaFuncAttributeMaxDynamicSharedMemorySize, ATT_SMEM);

    qkv_tc <<<dim3(18, 64), 256, GEMM_SMEM>>>(x, W_attn, b_attn);
    attn_tc<<<dim3(16, 48), 256, ATT_SMEM>>>();
    proj_tc<<<dim3(6, 64), 256, GEMM_SMEM>>>(W_proj, b_proj, out);
}

// round 6
// speedup vs baseline: 2.6516x; 1.4979x over previous
#include <cuda_runtime.h>
#include <cstdint>

#define B_  4
#define T_  2048
#define C_  768
#define H_  12
#define BH_ (B_*H_)
#define MT_ 8192

// Packed operands: each uint4 slot = {hi2(c,c+1), lo2(c,c+1), hi2(c+8,c+9), lo2(c+8,c+9)}
__device__ uint4 g_xp [MT_*192];      // x as A-slots       [row][48 ks16 * 4 t]
__device__ uint4 g_wap[2304*192];     // W_attn as B-slots  [n][...]
__device__ uint4 g_wpp[768*192];      // W_proj as B-slots
__device__ uint4 g_qp [BH_*2048*16];  // Q A-slots [bh*2048+tok][4 ks * 4 t] (pre-scaled)
__device__ uint4 g_kp [BH_*2048*16];  // K B-slots (pairs over d)
__device__ uint4 g_vp [BH_*32*1024];  // V B-slots per (bh,kb): [d][4 ks * 4 t] (pairs over tok)
__device__ uint4 g_op [MT_*192];      // attn out as A-slots for proj

// ---------------------------------------------------------------------------
__device__ __forceinline__ uint32_t h2(float x, float y) {
    uint32_t r; asm("cvt.rn.bf16x2.f32 %0, %1, %2;" : "=r"(r) : "f"(y), "f"(x));
    return r;   // low 16 = x, high 16 = y
}
__device__ __forceinline__ uint2 hl2(float x, float y) {
    uint2 r; r.x = h2(x, y);
    float xr = x - __uint_as_float(r.x << 16);
    float yr = y - __uint_as_float(r.x & 0xffff0000u);
    r.y = h2(xr, yr); return r;
}
__device__ __forceinline__ uint32_t smem_u32(const void* p) {
    uint32_t a;
    asm("{ .reg .u64 t; cvta.to.shared.u64 t, %1; cvt.u32.u64 %0, t; }" : "=r"(a) : "l"(p));
    return a;
}
__device__ __forceinline__ void cpa16(uint32_t dst, const void* src) {
    asm volatile("cp.async.cg.shared.global [%0], [%1], 16;"
                 :: "r"(dst), "l"(__cvta_generic_to_global(src)));
}
__device__ __forceinline__ void cpa_commit() { asm volatile("cp.async.commit_group;"); }
template<int N> __device__ __forceinline__ void cpa_wait() {
    asm volatile("cp.async.wait_group %0;" :: "n"(N));
}
__device__ __forceinline__ void mma16(float* d, const uint32_t* a, const uint32_t* b) {
    asm volatile("mma.sync.aligned.m16n8k16.row.col.f32.bf16.bf16.f32 "
        "{%0,%1,%2,%3}, {%4,%5,%6,%7}, {%8,%9}, {%0,%1,%2,%3};"
        : "+f"(d[0]), "+f"(d[1]), "+f"(d[2]), "+f"(d[3])
        : "r"(a[0]), "r"(a[1]), "r"(a[2]), "r"(a[3]), "r"(b[0]), "r"(b[1]));
}

// ---------------------------------------------------------------------------
// Pack kernels (one-time prepass)
// ---------------------------------------------------------------------------
__global__ __launch_bounds__(256) void pack_a(const float* __restrict__ src,
                                              uint4* __restrict__ dst)
{
    int idx = blockIdx.x * 256 + threadIdx.x;   // rows*192 total
    int r = idx / 192, s = idx - r * 192;
    int c = (s >> 2) * 16 + (s & 3) * 2;
    const float* p = src + (size_t)r * C_ + c;
    float2 v0 = *reinterpret_cast<const float2*>(p);
    float2 v8 = *reinterpret_cast<const float2*>(p + 8);
    uint2 a = hl2(v0.x, v0.y), b = hl2(v8.x, v8.y);
    dst[idx] = make_uint4(a.x, a.y, b.x, b.y);
}

__global__ __launch_bounds__(256) void pack_b(const float* __restrict__ W,
                                              uint4* __restrict__ dst, int N)
{
    __shared__ float sw[32][33];
    const int n0 = blockIdx.x * 32;
    const int kk = threadIdx.x >> 5, nn = threadIdx.x & 31;
    const int nl = threadIdx.x >> 3, s = threadIdx.x & 7;
    const int kb = (s >> 2) * 16 + (s & 3) * 2;
    for (int kc = 0; kc < 24; kc++) {
        __syncthreads();
#pragma unroll
        for (int p = 0; p < 4; p++)
            sw[kk + p * 8][nn] = W[(size_t)(kc * 32 + kk + p * 8) * N + n0 + nn];
        __syncthreads();
        uint2 a = hl2(sw[kb][nl], sw[kb + 1][nl]);
        uint2 b = hl2(sw[kb + 8][nl], sw[kb + 9][nl]);
        dst[(size_t)(n0 + nl) * 192 + kc * 8 + s] = make_uint4(a.x, a.y, b.x, b.y);
    }
}

// ---------------------------------------------------------------------------
// GEMM (bf16x3, slot-fed, cp.async double buffer). 128x128 tile, K=768.
// MODE 0: qkv -> packed g_qp/g_kp/g_vp.  MODE 1: proj -> fp32 out.
// ---------------------------------------------------------------------------
#define GST 12
#define GEMM_SMEM (6144*16)

template<int MODE>
__global__ __launch_bounds__(256, 1) void gemm_tc(const uint4* __restrict__ Ap,
                                                  const uint4* __restrict__ Bp,
                                                  const float* __restrict__ bias,
                                                  float* __restrict__ out)
{
    extern __shared__ uint4 sm4[];
    const uint32_t smb = smem_u32(sm4);
    const int tid = threadIdx.x, w = tid >> 5, lane = tid & 31, g = lane >> 2, t = lane & 3;
    const int M0 = blockIdx.y * 128, N0 = blockIdx.x * 128;
    const int mw = (w & 3) * 32, nw = (w >> 2) * 64;
    const int i_row = tid >> 3, i_s = tid & 7;

    float acc[2][8][4];
#pragma unroll
    for (int mt = 0; mt < 2; mt++)
#pragma unroll
        for (int nt = 0; nt < 8; nt++)
#pragma unroll
            for (int r = 0; r < 4; r++) acc[mt][nt][r] = 0.f;

    auto issue = [&](int c, int buf) {
        uint32_t dA = smb + (uint32_t)(buf * 1536) * 16;
        uint32_t dB = smb + (uint32_t)(3072 + buf * 1536) * 16;
#pragma unroll
        for (int j = 0; j < 4; j++) {
            int row = i_row + 32 * j;
            cpa16(dA + (uint32_t)(row * GST + i_s) * 16,
                  Ap + (size_t)(M0 + row) * 192 + c * 8 + i_s);
            cpa16(dB + (uint32_t)(row * GST + i_s) * 16,
                  Bp + (size_t)(N0 + row) * 192 + c * 8 + i_s);
        }
        cpa_commit();
    };

    issue(0, 0);
    issue(1, 1);

    for (int c = 0; c < 24; c++) {
        if (c < 23) cpa_wait<1>(); else cpa_wait<0>();
        __syncthreads();
        const int buf = c & 1;
        const uint4* sA = sm4 + buf * 1536;
        const uint4* sB = sm4 + 3072 + buf * 1536;
#pragma unroll
        for (int ks = 0; ks < 2; ks++) {
            uint32_t ah[2][4], al[2][4];
#pragma unroll
            for (int mt = 0; mt < 2; mt++) {
                uint4 u0 = sA[(mw + mt * 16 + g) * GST + ks * 4 + t];
                uint4 u1 = sA[(mw + mt * 16 + g + 8) * GST + ks * 4 + t];
                ah[mt][0] = u0.x; ah[mt][1] = u1.x; ah[mt][2] = u0.z; ah[mt][3] = u1.z;
                al[mt][0] = u0.y; al[mt][1] = u1.y; al[mt][2] = u0.w; al[mt][3] = u1.w;
            }
#pragma unroll
            for (int nt = 0; nt < 8; nt++) {
                uint4 ub = sB[(nw + nt * 8 + g) * GST + ks * 4 + t];
                uint32_t bh[2] = { ub.x, ub.z }, bl[2] = { ub.y, ub.w };
#pragma unroll
                for (int mt = 0; mt < 2; mt++) {
                    mma16(acc[mt][nt], ah[mt], bh);
                    mma16(acc[mt][nt], ah[mt], bl);
                    mma16(acc[mt][nt], al[mt], bh);
                }
            }
        }
        __syncthreads();
        if (c + 2 < 24) issue(c + 2, buf);
    }

    if (MODE == 1) {
#pragma unroll
        for (int mt = 0; mt < 2; mt++)
#pragma unroll
            for (int nt = 0; nt < 8; nt++)
#pragma unroll
                for (int rr = 0; rr < 2; rr++) {
                    int m_g = M0 + mw + mt * 16 + g + rr * 8;
                    int n_g = N0 + nw + nt * 8 + 2 * t;
                    float2 v = { acc[mt][nt][2 * rr] + bias[n_g],
                                 acc[mt][nt][2 * rr + 1] + bias[n_g + 1] };
                    *reinterpret_cast<float2*>(out + (size_t)m_g * C_ + n_g) = v;
                }
        return;
    }

    const int which = N0 / C_;     // whole 128-col block is q, k, or v
    if (which < 2) {
        uint4* dstp = which ? g_kp : g_qp;
        const float scl = which ? 1.f : 0.125f;
#pragma unroll
        for (int mt = 0; mt < 2; mt++)
#pragma unroll
            for (int nt = 0; nt < 8; nt++)
#pragma unroll
                for (int rr = 0; rr < 2; rr++) {
                    int m_g = M0 + mw + mt * 16 + g + rr * 8;
                    int n_g = N0 + nw + nt * 8 + 2 * t;
                    float v0 = (acc[mt][nt][2 * rr] + bias[n_g]) * scl;
                    float v1 = (acc[mt][nt][2 * rr + 1] + bias[n_g + 1]) * scl;
                    int cc = n_g - which * C_;
                    int h = cc >> 6, d = cc & 63;
                    int b = m_g >> 11, tok = m_g & 2047;
                    size_t sl = ((size_t)(b * H_ + h) * 2048 + tok) * 16
                              + (d >> 4) * 4 + ((d >> 1) & 3);
                    reinterpret_cast<uint2*>(dstp + sl)[(d >> 3) & 1] = hl2(v0, v1);
                }
    } else {
        // V: pairs run over tokens -> transpose via smem (mainloop done & synced)
        float* sv = reinterpret_cast<float*>(sm4);
#pragma unroll
        for (int mt = 0; mt < 2; mt++)
#pragma unroll
            for (int nt = 0; nt < 8; nt++)
#pragma unroll
                for (int rr = 0; rr < 2; rr++) {
                    int row = mw + mt * 16 + g + rr * 8;
                    int col = nw + nt * 8 + 2 * t;
                    sv[row * 133 + col]     = acc[mt][nt][2 * rr] + bias[N0 + col];
                    sv[row * 133 + col + 1] = acc[mt][nt][2 * rr + 1] + bias[N0 + col + 1];
                }
        __syncthreads();
        const int b = M0 >> 11, tok0 = M0 & 2047, h0 = (N0 - 2 * C_) >> 6;
#pragma unroll
        for (int r = 0; r < 32; r++) {
            int id = tid + 256 * r;            // 8192 token-pairs x channels
            int cloc = id >> 6, tl0 = (id & 63) * 2;
            float v0 = sv[tl0 * 133 + cloc];
            float v1 = sv[(tl0 + 1) * 133 + cloc];
            int h = h0 + (cloc >> 6), d = cloc & 63;
            int tokg = tok0 + tl0, kb = tokg >> 6, tl = tokg & 63;
            size_t sl = (((size_t)((b * H_ + h) * 32) + kb) * 64 + d) * 16
                      + (tl >> 4) * 4 + ((tl >> 1) & 3);
            reinterpret_cast<uint2*>(g_vp + sl)[(tl >> 3) & 1] = hl2(v0, v1);
        }
    }
}

// ---------------------------------------------------------------------------
// Flash attention (bf16x3, slot-fed, P stays in registers).
// Block = (bh, 128-row q tile), 8 warps x 16 rows. k-tile = 64.
// smem u4: Q 128x20 | { K 64x20, V 64x20 } x2 bufs
// ---------------------------------------------------------------------------
#define QST 20
#define ATT_SMEM (7680*16)

__global__ __launch_bounds__(256, 1) void attn_tc()
{
    extern __shared__ uint4 sm4[];
    const uint32_t smb = smem_u32(sm4);
    const int bh = blockIdx.y;
    const int qb = (gridDim.x - 1) - blockIdx.x;   // heavy q-tiles first
    const int tid = threadIdx.x, w = tid >> 5, lane = tid & 31, g = lane >> 2, t = lane & 3;
    const int m0 = w * 16;
    const int i_n = tid >> 4, i_s = tid & 15;

    // Q slots (group 0, committed by first issueKV)
#pragma unroll
    for (int j = 0; j < 8; j++) {
        int row = i_n + 16 * j;
        cpa16(smb + (uint32_t)(row * QST + i_s) * 16,
              g_qp + ((size_t)bh * 2048 + qb * 128 + row) * 16 + i_s);
    }
    auto issueKV = [&](int kb, int buf) {
        uint32_t dK = smb + (uint32_t)(2560 + buf * 2560) * 16;
        uint32_t dV = dK + 1280u * 16;
#pragma unroll
        for (int j = 0; j < 4; j++) {
            int n = i_n + 16 * j;
            cpa16(dK + (uint32_t)(n * QST + i_s) * 16,
                  g_kp + ((size_t)bh * 2048 + kb * 64 + n) * 16 + i_s);
            cpa16(dV + (uint32_t)(n * QST + i_s) * 16,
                  g_vp + (size_t)(bh * 32 + kb) * 1024 + n * 16 + i_s);
        }
        cpa_commit();
    };

    const int nkb = 2 * qb + 2;
    issueKV(0, 0);
    issueKV(1, 1);

    float o[8][4];
#pragma unroll
    for (int nt = 0; nt < 8; nt++)
#pragma unroll
        for (int r = 0; r < 4; r++) o[nt][r] = 0.f;
    float mrow[2] = { -1e30f, -1e30f }, lrow[2] = { 0.f, 0.f };

    for (int kb = 0; kb < nkb; kb++) {
        if (kb < nkb - 1) cpa_wait<1>(); else cpa_wait<0>();
        __syncthreads();
        const int buf = kb & 1;
        const uint4* sK = sm4 + 2560 + buf * 2560;
        const uint4* sV = sK + 1280;

        // S = Q @ K^T
        float s[8][4];
#pragma unroll
        for (int nt = 0; nt < 8; nt++)
#pragma unroll
            for (int r = 0; r < 4; r++) s[nt][r] = 0.f;
#pragma unroll
        for (int ks = 0; ks < 4; ks++) {
            uint4 u0 = sm4[(m0 + g) * QST + ks * 4 + t];
            uint4 u1 = sm4[(m0 + g + 8) * QST + ks * 4 + t];
            uint32_t qh[4] = { u0.x, u1.x, u0.z, u1.z };
            uint32_t ql[4] = { u0.y, u1.y, u0.w, u1.w };
#pragma unroll
            for (int nt = 0; nt < 8; nt++) {
                uint4 ub = sK[(nt * 8 + g) * QST + ks * 4 + t];
                uint32_t kh[2] = { ub.x, ub.z }, kl[2] = { ub.y, ub.w };
                mma16(s[nt], qh, kh);
                mma16(s[nt], qh, kl);
                mma16(s[nt], ql, kh);
            }
        }

        // causal mask (only last two k-tiles can cross the diagonal)
        if (kb >= 2 * qb) {
            int qr0 = qb * 128 + m0 + g;
#pragma unroll
            for (int nt = 0; nt < 8; nt++) {
                int col = kb * 64 + nt * 8 + 2 * t;
                if (col > qr0)         s[nt][0] = -1e30f;
                if (col + 1 > qr0)     s[nt][1] = -1e30f;
                if (col > qr0 + 8)     s[nt][2] = -1e30f;
                if (col + 1 > qr0 + 8) s[nt][3] = -1e30f;
            }
        }

        // online softmax (rows g, g+8 live in 4-lane shuffle groups)
        float pm0 = -1e30f, pm1 = -1e30f;
#pragma unroll
        for (int nt = 0; nt < 8; nt++) {
            pm0 = fmaxf(pm0, fmaxf(s[nt][0], s[nt][1]));
            pm1 = fmaxf(pm1, fmaxf(s[nt][2], s[nt][3]));
        }
        pm0 = fmaxf(pm0, __shfl_xor_sync(0xffffffffu, pm0, 1));
        pm0 = fmaxf(pm0, __shfl_xor_sync(0xffffffffu, pm0, 2));
        pm1 = fmaxf(pm1, __shfl_xor_sync(0xffffffffu, pm1, 1));
        pm1 = fmaxf(pm1, __shfl_xor_sync(0xffffffffu, pm1, 2));
        float mn0 = fmaxf(mrow[0], pm0), mn1 = fmaxf(mrow[1], pm1);
        float al0 = __expf(mrow[0] - mn0), al1 = __expf(mrow[1] - mn1);
        mrow[0] = mn0; mrow[1] = mn1;
        float sum0 = 0.f, sum1 = 0.f;
#pragma unroll
        for (int nt = 0; nt < 8; nt++) {
            s[nt][0] = __expf(s[nt][0] - mn0); sum0 += s[nt][0];
            s[nt][1] = __expf(s[nt][1] - mn0); sum0 += s[nt][1];
            s[nt][2] = __expf(s[nt][2] - mn1); sum1 += s[nt][2];
            s[nt][3] = __expf(s[nt][3] - mn1); sum1 += s[nt][3];
        }
        sum0 += __shfl_xor_sync(0xffffffffu, sum0, 1);
        sum0 += __shfl_xor_sync(0xffffffffu, sum0, 2);
        sum1 += __shfl_xor_sync(0xffffffffu, sum1, 1);
        sum1 += __shfl_xor_sync(0xffffffffu, sum1, 2);
        lrow[0] = lrow[0] * al0 + sum0;
        lrow[1] = lrow[1] * al1 + sum1;
#pragma unroll
        for (int nt = 0; nt < 8; nt++) {
            o[nt][0] *= al0; o[nt][1] *= al0;
            o[nt][2] *= al1; o[nt][3] *= al1;
        }

        // O += P @ V  — S D-fragment IS the PV A-fragment (just split to bf16)
#pragma unroll
        for (int ks = 0; ks < 4; ks++) {
            uint2 p0 = hl2(s[2 * ks][0], s[2 * ks][1]);
            uint2 p1 = hl2(s[2 * ks][2], s[2 * ks][3]);
            uint2 p2 = hl2(s[2 * ks + 1][0], s[2 * ks + 1][1]);
            uint2 p3 = hl2(s[2 * ks + 1][2], s[2 * ks + 1][3]);
            uint32_t ph[4] = { p0.x, p1.x, p2.x, p3.x };
            uint32_t pl[4] = { p0.y, p1.y, p2.y, p3.y };
#pragma unroll
            for (int nt = 0; nt < 8; nt++) {
                uint4 ub = sV[(nt * 8 + g) * QST + ks * 4 + t];
                uint32_t vh[2] = { ub.x, ub.z }, vl[2] = { ub.y, ub.w };
                mma16(o[nt], ph, vh);
                mma16(o[nt], ph, vl);
                mma16(o[nt], pl, vh);
            }
        }
        __syncthreads();
        if (kb + 2 < nkb) issueKV(kb + 2, buf);
    }

    // epilogue: normalize, write packed A-slots for proj
    float inv0 = 1.f / lrow[0], inv1 = 1.f / lrow[1];
    const int bI = bh / H_, hI = bh - bI * H_;
#pragma unroll
    for (int nt = 0; nt < 8; nt++) {
        int c = hI * 64 + nt * 8 + 2 * t;
#pragma unroll
        for (int rr = 0; rr < 2; rr++) {
            float iv = rr ? inv1 : inv0;
            int row = qb * 128 + m0 + g + rr * 8;
            size_t sl = ((size_t)bI * 2048 + row) * 192 + (c >> 4) * 4 + ((c >> 1) & 3);
            reinterpret_cast<uint2*>(g_op + sl)[(c >> 3) & 1] =
                hl2(o[nt][2 * rr] * iv, o[nt][2 * rr + 1] * iv);
        }
    }
}

// ---------------------------------------------------------------------------
extern "C" void kernel_launch(void* const* d_in, const int* in_sizes, int n_in,
                              void* d_out, int out_size)
{
    const float* x      = (const float*)d_in[0];
    const float* W_attn = (const float*)d_in[1];
    const float* b_attn = (const float*)d_in[2];
    const float* W_proj = (const float*)d_in[3];
    const float* b_proj = (const float*)d_in[4];
    float* out = (float*)d_out;

    uint4 *xp, *wap, *wpp, *op;
    cudaGetSymbolAddress((void**)&xp,  g_xp);
    cudaGetSymbolAddress((void**)&wap, g_wap);
    cudaGetSymbolAddress((void**)&wpp, g_wpp);
    cudaGetSymbolAddress((void**)&op,  g_op);

    cudaFuncSetAttribute(gemm_tc<0>, cudaFuncAttributeMaxDynamicSharedMemorySize, GEMM_SMEM);
    cudaFuncSetAttribute(gemm_tc<1>, cudaFuncAttributeMaxDynamicSharedMemorySize, GEMM_SMEM);
    cudaFuncSetAttribute(attn_tc,    cudaFuncAttributeMaxDynamicSharedMemorySize, ATT_SMEM);

    pack_a<<<MT_ * 192 / 256, 256>>>(x, xp);
    pack_b<<<72, 256>>>(W_attn, wap, 3 * C_);
    pack_b<<<24, 256>>>(W_proj, wpp, C_);
    gemm_tc<0><<<dim3(18, 64), 256, GEMM_SMEM>>>(xp, wap, b_attn, nullptr);
    attn_tc<<<dim3(16, 48), 256, ATT_SMEM>>>();
    gemm_tc<1><<<dim3(6, 64), 256, GEMM_SMEM>>>(op, wpp, b_proj, out);
}

// round 7
// speedup vs baseline: 2.7560x; 1.0393x over previous
#include <cuda_runtime.h>
#include <cstdint>

#define B_  4
#define T_  2048
#define C_  768
#define H_  12
#define BH_ (B_*H_)
#define MT_ 8192

// Packed operands: each uint4 slot = {hi2(c,c+1), lo2(c,c+1), hi2(c+8,c+9), lo2(c+8,c+9)}
__device__ uint4 g_xp [MT_*192];      // x as A-slots
__device__ uint4 g_wap[2304*192];     // W_attn as B-slots
__device__ uint4 g_wpp[768*192];      // W_proj as B-slots
__device__ uint4 g_qp [BH_*2048*16];  // Q A-slots (pre-scaled)
__device__ uint4 g_kp [BH_*2048*16];  // K B-slots
__device__ uint4 g_vp [BH_*32*1024];  // V B-slots per (bh,kb): [d][slots]
__device__ uint4 g_op [MT_*192];      // attn out as A-slots for proj

// ---------------------------------------------------------------------------
__device__ __forceinline__ uint32_t h2(float x, float y) {
    uint32_t r; asm("cvt.rn.bf16x2.f32 %0, %1, %2;" : "=r"(r) : "f"(y), "f"(x));
    return r;
}
__device__ __forceinline__ uint2 hl2(float x, float y) {
    uint2 r; r.x = h2(x, y);
    float xr = x - __uint_as_float(r.x << 16);
    float yr = y - __uint_as_float(r.x & 0xffff0000u);
    r.y = h2(xr, yr); return r;
}
__device__ __forceinline__ uint32_t smem_u32(const void* p) {
    uint32_t a;
    asm("{ .reg .u64 t; cvta.to.shared.u64 t, %1; cvt.u32.u64 %0, t; }" : "=r"(a) : "l"(p));
    return a;
}
__device__ __forceinline__ void cpa16(uint32_t dst, const void* src) {
    asm volatile("cp.async.cg.shared.global [%0], [%1], 16;"
                 :: "r"(dst), "l"(__cvta_generic_to_global(src)));
}
__device__ __forceinline__ void cpa_commit() { asm volatile("cp.async.commit_group;"); }
template<int N> __device__ __forceinline__ void cpa_wait() {
    asm volatile("cp.async.wait_group %0;" :: "n"(N));
}
__device__ __forceinline__ void mma16(float* d, const uint32_t* a, const uint32_t* b) {
    asm volatile("mma.sync.aligned.m16n8k16.row.col.f32.bf16.bf16.f32 "
        "{%0,%1,%2,%3}, {%4,%5,%6,%7}, {%8,%9}, {%0,%1,%2,%3};"
        : "+f"(d[0]), "+f"(d[1]), "+f"(d[2]), "+f"(d[3])
        : "r"(a[0]), "r"(a[1]), "r"(a[2]), "r"(a[3]), "r"(b[0]), "r"(b[1]));
}

// ---------------------------------------------------------------------------
// Pack kernels (one-time prepass)
// ---------------------------------------------------------------------------
__global__ __launch_bounds__(256) void pack_a(const float* __restrict__ src,
                                              uint4* __restrict__ dst)
{
    int idx = blockIdx.x * 256 + threadIdx.x;
    int r = idx / 192, s = idx - r * 192;
    int c = (s >> 2) * 16 + (s & 3) * 2;
    const float* p = src + (size_t)r * C_ + c;
    float2 v0 = *reinterpret_cast<const float2*>(p);
    float2 v8 = *reinterpret_cast<const float2*>(p + 8);
    uint2 a = hl2(v0.x, v0.y), b = hl2(v8.x, v8.y);
    dst[idx] = make_uint4(a.x, a.y, b.x, b.y);
}

__global__ __launch_bounds__(256) void pack_b(const float* __restrict__ W,
                                              uint4* __restrict__ dst, int N)
{
    __shared__ float sw[32][33];
    const int n0 = blockIdx.x * 32;
    const int kk = threadIdx.x >> 5, nn = threadIdx.x & 31;
    const int nl = threadIdx.x >> 3, s = threadIdx.x & 7;
    const int kb = (s >> 2) * 16 + (s & 3) * 2;
    for (int kc = 0; kc < 24; kc++) {
        __syncthreads();
#pragma unroll
        for (int p = 0; p < 4; p++)
            sw[kk + p * 8][nn] = W[(size_t)(kc * 32 + kk + p * 8) * N + n0 + nn];
        __syncthreads();
        uint2 a = hl2(sw[kb][nl], sw[kb + 1][nl]);
        uint2 b = hl2(sw[kb + 8][nl], sw[kb + 9][nl]);
        dst[(size_t)(n0 + nl) * 192 + kc * 8 + s] = make_uint4(a.x, a.y, b.x, b.y);
    }
}

// ---------------------------------------------------------------------------
// GEMM (bf16x3, slot-fed, 3-stage cp.async, term-major MMA). 128x128, K=768.
// ---------------------------------------------------------------------------
#define GST 12
#define GEMM_SMEM (9216*16)   // 3 x (A 1536 + B 1536) u4 = 147456 B

template<int MODE>
__global__ __launch_bounds__(256, 1) void gemm_tc(const uint4* __restrict__ Ap,
                                                  const uint4* __restrict__ Bp,
                                                  const float* __restrict__ bias,
                                                  float* __restrict__ out)
{
    extern __shared__ uint4 sm4[];
    const uint32_t smb = smem_u32(sm4);
    const int tid = threadIdx.x, w = tid >> 5, lane = tid & 31, g = lane >> 2, t = lane & 3;
    const int M0 = blockIdx.y * 128, N0 = blockIdx.x * 128;
    const int mw = (w & 3) * 32, nw = (w >> 2) * 64;
    const int i_row = tid >> 3, i_s = tid & 7;

    const uint4* aBase = Ap + (size_t)(M0 + i_row) * 192 + i_s;
    const uint4* bBase = Bp + (size_t)(N0 + i_row) * 192 + i_s;
    const uint32_t dA0 = smb + (uint32_t)(i_row * GST + i_s) * 16;
    const uint32_t dB0 = dA0 + 4608u * 16;

    float acc[2][8][4];
#pragma unroll
    for (int mt = 0; mt < 2; mt++)
#pragma unroll
        for (int nt = 0; nt < 8; nt++)
#pragma unroll
            for (int r = 0; r < 4; r++) acc[mt][nt][r] = 0.f;

    auto issue = [&](int c, int buf) {
        uint32_t o = (uint32_t)buf * 1536u * 16u;
#pragma unroll
        for (int j = 0; j < 4; j++) {
            cpa16(dA0 + o + (uint32_t)(j * 32 * GST) * 16, aBase + j * 32 * 192 + c * 8);
            cpa16(dB0 + o + (uint32_t)(j * 32 * GST) * 16, bBase + j * 32 * 192 + c * 8);
        }
        cpa_commit();
    };

    issue(0, 0);
    issue(1, 1);

#pragma unroll 1
    for (int c3 = 0; c3 < 8; c3++) {
#pragma unroll
        for (int sub = 0; sub < 3; sub++) {
            const int c = c3 * 3 + sub;
            if (c < 23) cpa_wait<1>(); else cpa_wait<0>();
            __syncthreads();
            if (c < 22) issue(c + 2, (sub + 2) % 3);
            const uint4* sA = sm4 + sub * 1536;
            const uint4* sB = sm4 + 4608 + sub * 1536;
#pragma unroll
            for (int ks = 0; ks < 2; ks++) {
                uint32_t ah[2][4], al[2][4], bhf[8][2], blf[8][2];
#pragma unroll
                for (int mt = 0; mt < 2; mt++) {
                    uint4 u0 = sA[(mw + mt * 16 + g) * GST + ks * 4 + t];
                    uint4 u1 = sA[(mw + mt * 16 + g + 8) * GST + ks * 4 + t];
                    ah[mt][0] = u0.x; ah[mt][1] = u1.x; ah[mt][2] = u0.z; ah[mt][3] = u1.z;
                    al[mt][0] = u0.y; al[mt][1] = u1.y; al[mt][2] = u0.w; al[mt][3] = u1.w;
                }
#pragma unroll
                for (int nt = 0; nt < 8; nt++) {
                    uint4 ub = sB[(nw + nt * 8 + g) * GST + ks * 4 + t];
                    bhf[nt][0] = ub.x; bhf[nt][1] = ub.z;
                    blf[nt][0] = ub.y; blf[nt][1] = ub.w;
                }
#pragma unroll
                for (int nt = 0; nt < 8; nt++) {
                    mma16(acc[0][nt], ah[0], bhf[nt]);
                    mma16(acc[1][nt], ah[1], bhf[nt]);
                }
#pragma unroll
                for (int nt = 0; nt < 8; nt++) {
                    mma16(acc[0][nt], ah[0], blf[nt]);
                    mma16(acc[1][nt], ah[1], blf[nt]);
                }
#pragma unroll
                for (int nt = 0; nt < 8; nt++) {
                    mma16(acc[0][nt], al[0], bhf[nt]);
                    mma16(acc[1][nt], al[1], bhf[nt]);
                }
            }
        }
    }

    if (MODE == 1) {
#pragma unroll
        for (int mt = 0; mt < 2; mt++)
#pragma unroll
            for (int nt = 0; nt < 8; nt++)
#pragma unroll
                for (int rr = 0; rr < 2; rr++) {
                    int m_g = M0 + mw + mt * 16 + g + rr * 8;
                    int n_g = N0 + nw + nt * 8 + 2 * t;
                    float2 v = { acc[mt][nt][2 * rr] + bias[n_g],
                                 acc[mt][nt][2 * rr + 1] + bias[n_g + 1] };
                    *reinterpret_cast<float2*>(out + (size_t)m_g * C_ + n_g) = v;
                }
        return;
    }

    const int which = N0 / C_;
    if (which < 2) {
        uint4* dstp = which ? g_kp : g_qp;
        const float scl = which ? 1.f : 0.125f;
#pragma unroll
        for (int mt = 0; mt < 2; mt++)
#pragma unroll
            for (int nt = 0; nt < 8; nt++)
#pragma unroll
                for (int rr = 0; rr < 2; rr++) {
                    int m_g = M0 + mw + mt * 16 + g + rr * 8;
                    int n_g = N0 + nw + nt * 8 + 2 * t;
                    float v0 = (acc[mt][nt][2 * rr] + bias[n_g]) * scl;
                    float v1 = (acc[mt][nt][2 * rr + 1] + bias[n_g + 1]) * scl;
                    int cc = n_g - which * C_;
                    int h = cc >> 6, d = cc & 63;
                    int b = m_g >> 11, tok = m_g & 2047;
                    size_t sl = ((size_t)(b * H_ + h) * 2048 + tok) * 16
                              + (d >> 4) * 4 + ((d >> 1) & 3);
                    reinterpret_cast<uint2*>(dstp + sl)[(d >> 3) & 1] = hl2(v0, v1);
                }
    } else {
        __syncthreads();   // all warps done reading smem before reuse
        float* sv = reinterpret_cast<float*>(sm4);
#pragma unroll
        for (int mt = 0; mt < 2; mt++)
#pragma unroll
            for (int nt = 0; nt < 8; nt++)
#pragma unroll
                for (int rr = 0; rr < 2; rr++) {
                    int row = mw + mt * 16 + g + rr * 8;
                    int col = nw + nt * 8 + 2 * t;
                    sv[row * 133 + col]     = acc[mt][nt][2 * rr] + bias[N0 + col];
                    sv[row * 133 + col + 1] = acc[mt][nt][2 * rr + 1] + bias[N0 + col + 1];
                }
        __syncthreads();
        const int b = M0 >> 11, tok0 = M0 & 2047, h0 = (N0 - 2 * C_) >> 6;
#pragma unroll
        for (int r = 0; r < 32; r++) {
            int id = tid + 256 * r;
            int cloc = id >> 6, tl0 = (id & 63) * 2;
            float v0 = sv[tl0 * 133 + cloc];
            float v1 = sv[(tl0 + 1) * 133 + cloc];
            int h = h0 + (cloc >> 6), d = cloc & 63;
            int tokg = tok0 + tl0, kb = tokg >> 6, tl = tokg & 63;
            size_t sl = (((size_t)((b * H_ + h) * 32) + kb) * 64 + d) * 16
                      + (tl >> 4) * 4 + ((tl >> 1) & 3);
            reinterpret_cast<uint2*>(g_vp + sl)[(tl >> 3) & 1] = hl2(v0, v1);
        }
    }
}

// ---------------------------------------------------------------------------
// Flash attention (bf16x3, 3-stage cp.async, term-major MMA, P in registers).
// Block = (bh, 128-row q tile). smem u4: Q 128x20 | {K 64x20, V 64x20} x3
// ---------------------------------------------------------------------------
#define QST 20
#define ATT_SMEM (10240*16)   // 163840 B

__global__ __launch_bounds__(256, 1) void attn_tc()
{
    extern __shared__ uint4 sm4[];
    const uint32_t smb = smem_u32(sm4);
    const int bh = blockIdx.y;
    const int qb = (gridDim.x - 1) - blockIdx.x;
    const int tid = threadIdx.x, w = tid >> 5, lane = tid & 31, g = lane >> 2, t = lane & 3;
    const int m0 = w * 16;
    const int i_n = tid >> 4, i_s = tid & 15;

    const uint4* qBase = g_qp + ((size_t)bh * 2048 + qb * 128 + i_n) * 16 + i_s;
    const uint4* kBase = g_kp + ((size_t)bh * 2048 + i_n) * 16 + i_s;
    const uint4* vBase = g_vp + (size_t)(bh * 32) * 1024 + i_n * 16 + i_s;
    const uint32_t dQ0 = smb + (uint32_t)(i_n * QST + i_s) * 16;
    const uint32_t dK0 = smb + (uint32_t)(2560 + i_n * QST + i_s) * 16;

    // Q slots join group 0 (committed by first issueKV)
#pragma unroll
    for (int j = 0; j < 8; j++)
        cpa16(dQ0 + (uint32_t)(j * 16 * QST) * 16, qBase + j * 16 * 16);

    auto issueKV = [&](int kb, int buf) {
        uint32_t o = (uint32_t)buf * 2560u * 16u;
#pragma unroll
        for (int j = 0; j < 4; j++) {
            cpa16(dK0 + o + (uint32_t)(j * 16 * QST) * 16, kBase + kb * 1024 + j * 256);
            cpa16(dK0 + o + (uint32_t)(1280 + j * 16 * QST) * 16, vBase + kb * 1024 + j * 256);
        }
        cpa_commit();
    };

    const int nkb = 2 * qb + 2;
    issueKV(0, 0);
    issueKV(1, 1);

    float o[8][4];
#pragma unroll
    for (int nt = 0; nt < 8; nt++)
#pragma unroll
        for (int r = 0; r < 4; r++) o[nt][r] = 0.f;
    float mrow[2] = { -1e30f, -1e30f }, lrow[2] = { 0.f, 0.f };

    int cbuf = 0, ibuf = 2;
    for (int kb = 0; kb < nkb; kb++) {
        if (kb < nkb - 1) cpa_wait<1>(); else cpa_wait<0>();
        __syncthreads();
        if (kb + 2 < nkb) issueKV(kb + 2, ibuf);
        const uint4* sK = sm4 + 2560 + cbuf * 2560;
        const uint4* sV = sK + 1280;

        // ---- S = Q @ K^T (term-major) ----
        float s[8][4];
#pragma unroll
        for (int nt = 0; nt < 8; nt++)
#pragma unroll
            for (int r = 0; r < 4; r++) s[nt][r] = 0.f;
#pragma unroll
        for (int ks = 0; ks < 4; ks++) {
            uint4 u0 = sm4[(m0 + g) * QST + ks * 4 + t];
            uint4 u1 = sm4[(m0 + g + 8) * QST + ks * 4 + t];
            uint32_t qh[4] = { u0.x, u1.x, u0.z, u1.z };
            uint32_t ql[4] = { u0.y, u1.y, u0.w, u1.w };
            uint32_t kh[8][2], kl[8][2];
#pragma unroll
            for (int nt = 0; nt < 8; nt++) {
                uint4 ub = sK[(nt * 8 + g) * QST + ks * 4 + t];
                kh[nt][0] = ub.x; kh[nt][1] = ub.z;
                kl[nt][0] = ub.y; kl[nt][1] = ub.w;
            }
#pragma unroll
            for (int nt = 0; nt < 8; nt++) mma16(s[nt], qh, kh[nt]);
#pragma unroll
            for (int nt = 0; nt < 8; nt++) mma16(s[nt], qh, kl[nt]);
#pragma unroll
            for (int nt = 0; nt < 8; nt++) mma16(s[nt], ql, kh[nt]);
        }

        // ---- causal mask ----
        if (kb >= 2 * qb) {
            int qr0 = qb * 128 + m0 + g;
#pragma unroll
            for (int nt = 0; nt < 8; nt++) {
                int col = kb * 64 + nt * 8 + 2 * t;
                if (col > qr0)         s[nt][0] = -1e30f;
                if (col + 1 > qr0)     s[nt][1] = -1e30f;
                if (col > qr0 + 8)     s[nt][2] = -1e30f;
                if (col + 1 > qr0 + 8) s[nt][3] = -1e30f;
            }
        }

        // ---- online softmax ----
        float pm0 = -1e30f, pm1 = -1e30f;
#pragma unroll
        for (int nt = 0; nt < 8; nt++) {
            pm0 = fmaxf(pm0, fmaxf(s[nt][0], s[nt][1]));
            pm1 = fmaxf(pm1, fmaxf(s[nt][2], s[nt][3]));
        }
        pm0 = fmaxf(pm0, __shfl_xor_sync(0xffffffffu, pm0, 1));
        pm0 = fmaxf(pm0, __shfl_xor_sync(0xffffffffu, pm0, 2));
        pm1 = fmaxf(pm1, __shfl_xor_sync(0xffffffffu, pm1, 1));
        pm1 = fmaxf(pm1, __shfl_xor_sync(0xffffffffu, pm1, 2));
        float mn0 = fmaxf(mrow[0], pm0), mn1 = fmaxf(mrow[1], pm1);
        float al0 = __expf(mrow[0] - mn0), al1 = __expf(mrow[1] - mn1);
        mrow[0] = mn0; mrow[1] = mn1;
        float sum0 = 0.f, sum1 = 0.f;
#pragma unroll
        for (int nt = 0; nt < 8; nt++) {
            s[nt][0] = __expf(s[nt][0] - mn0); sum0 += s[nt][0];
            s[nt][1] = __expf(s[nt][1] - mn0); sum0 += s[nt][1];
            s[nt][2] = __expf(s[nt][2] - mn1); sum1 += s[nt][2];
            s[nt][3] = __expf(s[nt][3] - mn1); sum1 += s[nt][3];
        }
        sum0 += __shfl_xor_sync(0xffffffffu, sum0, 1);
        sum0 += __shfl_xor_sync(0xffffffffu, sum0, 2);
        sum1 += __shfl_xor_sync(0xffffffffu, sum1, 1);
        sum1 += __shfl_xor_sync(0xffffffffu, sum1, 2);
        lrow[0] = lrow[0] * al0 + sum0;
        lrow[1] = lrow[1] * al1 + sum1;
#pragma unroll
        for (int nt = 0; nt < 8; nt++) {
            o[nt][0] *= al0; o[nt][1] *= al0;
            o[nt][2] *= al1; o[nt][3] *= al1;
        }

        // ---- O += P @ V (term-major; S D-frag IS the PV A-frag) ----
#pragma unroll
        for (int ks = 0; ks < 4; ks++) {
            uint2 p0 = hl2(s[2 * ks][0], s[2 * ks][1]);
            uint2 p1 = hl2(s[2 * ks][2], s[2 * ks][3]);
            uint2 p2 = hl2(s[2 * ks + 1][0], s[2 * ks + 1][1]);
            uint2 p3 = hl2(s[2 * ks + 1][2], s[2 * ks + 1][3]);
            uint32_t ph[4] = { p0.x, p1.x, p2.x, p3.x };
            uint32_t pl[4] = { p0.y, p1.y, p2.y, p3.y };
            uint32_t vh[8][2], vl[8][2];
#pragma unroll
            for (int nt = 0; nt < 8; nt++) {
                uint4 ub = sV[(nt * 8 + g) * QST + ks * 4 + t];
                vh[nt][0] = ub.x; vh[nt][1] = ub.z;
                vl[nt][0] = ub.y; vl[nt][1] = ub.w;
            }
#pragma unroll
            for (int nt = 0; nt < 8; nt++) mma16(o[nt], ph, vh[nt]);
#pragma unroll
            for (int nt = 0; nt < 8; nt++) mma16(o[nt], ph, vl[nt]);
#pragma unroll
            for (int nt = 0; nt < 8; nt++) mma16(o[nt], pl, vh[nt]);
        }
        cbuf = (cbuf == 2) ? 0 : cbuf + 1;
        ibuf = (ibuf == 2) ? 0 : ibuf + 1;
    }

    // ---- epilogue: normalize, write packed A-slots for proj ----
    float inv0 = 1.f / lrow[0], inv1 = 1.f / lrow[1];
    const int bI = bh / H_, hI = bh - bI * H_;
#pragma unroll
    for (int nt = 0; nt < 8; nt++) {
        int c = hI * 64 + nt * 8 + 2 * t;
#pragma unroll
        for (int rr = 0; rr < 2; rr++) {
            float iv = rr ? inv1 : inv0;
            int row = qb * 128 + m0 + g + rr * 8;
            size_t sl = ((size_t)bI * 2048 + row) * 192 + (c >> 4) * 4 + ((c >> 1) & 3);
            reinterpret_cast<uint2*>(g_op + sl)[(c >> 3) & 1] =
                hl2(o[nt][2 * rr] * iv, o[nt][2 * rr + 1] * iv);
        }
    }
}

// ---------------------------------------------------------------------------
extern "C" void kernel_launch(void* const* d_in, const int* in_sizes, int n_in,
                              void* d_out, int out_size)
{
    const float* x      = (const float*)d_in[0];
    const float* W_attn = (const float*)d_in[1];
    const float* b_attn = (const float*)d_in[2];
    const float* W_proj = (const float*)d_in[3];
    const float* b_proj = (const float*)d_in[4];
    float* out = (float*)d_out;

    uint4 *xp, *wap, *wpp, *op;
    cudaGetSymbolAddress((void**)&xp,  g_xp);
    cudaGetSymbolAddress((void**)&wap, g_wap);
    cudaGetSymbolAddress((void**)&wpp, g_wpp);
    cudaGetSymbolAddress((void**)&op,  g_op);

    cudaFuncSetAttribute(gemm_tc<0>, cudaFuncAttributeMaxDynamicSharedMemorySize, GEMM_SMEM);
    cudaFuncSetAttribute(gemm_tc<1>, cudaFuncAttributeMaxDynamicSharedMemorySize, GEMM_SMEM);
    cudaFuncSetAttribute(attn_tc,    cudaFuncAttributeMaxDynamicSharedMemorySize, ATT_SMEM);

    pack_a<<<MT_ * 192 / 256, 256>>>(x, xp);
    pack_b<<<72, 256>>>(W_attn, wap, 3 * C_);
    pack_b<<<24, 256>>>(W_proj, wpp, C_);
    gemm_tc<0><<<dim3(18, 64), 256, GEMM_SMEM>>>(xp, wap, b_attn, nullptr);
    attn_tc<<<dim3(16, 48), 256, ATT_SMEM>>>();
    gemm_tc<1><<<dim3(6, 64), 256, GEMM_SMEM>>>(op, wpp, b_proj, out);
}